// round 1
// baseline (speedup 1.0000x reference)
#include <cuda_runtime.h>
#include <cuda_bf16.h>

// Problem constants (fixed by the reference)
#define BB 2
#define LL 2048
#define DM 768
#define DI 1536
#define DS 16
#define DC 4
#define ML (BB*LL)          // 4096 rows

// ---------------- scratch (device globals; no allocs allowed) ----------------
__device__ float g_xin[ML*DI];   // x_inner after W_in split
__device__ float g_z  [ML*DI];   // z gate
__device__ float g_xc [ML*DI];   // conv+silu output
__device__ float g_Bm [ML*DS];   // B matrix
__device__ float g_Cm [ML*DS];   // C matrix
__device__ float g_dt [ML*DI];   // softplus(dt)
__device__ float g_y  [ML*DI];   // scan output, gated

// ---------------- generic 128x128 tiled fp32 GEMM -----------------------------
// MODE 1: A = param (x),  B = W_in,  out -> split g_xin / g_z   (N = 2*DI)
// MODE 2: A = g_xc,       B = W_dt,  out -> softplus(.+bias) -> g_dt
// MODE 3: A = g_y,        B = W_out, out -> C0 param (d_out)
template <int MODE>
__global__ void __launch_bounds__(256)
gemm128(const float* __restrict__ Ain, const float* __restrict__ Bin,
        float* __restrict__ C0, const float* __restrict__ bias,
        int M, int N, int K)
{
    const float* __restrict__ Aptr =
        (MODE == 1) ? Ain : (MODE == 2) ? (const float*)g_xc : (const float*)g_y;

    const int bm = blockIdx.y * 128;
    const int bn = blockIdx.x * 128;
    const int tx = threadIdx.x;     // 0..15
    const int ty = threadIdx.y;     // 0..15
    const int tid = ty * 16 + tx;

    __shared__ float As[8][128];
    __shared__ float Bs[8][128];

    float acc[8][8];
#pragma unroll
    for (int i = 0; i < 8; i++)
#pragma unroll
        for (int j = 0; j < 8; j++) acc[i][j] = 0.f;

    const int ar  = tid >> 1;         // 0..127 (row within A tile)
    const int ak  = (tid & 1) * 4;    // 0 or 4 (k offset)
    const int bk  = tid >> 5;         // 0..7   (k row within B tile)
    const int bn4 = (tid & 31) * 4;   // 0..124 (col within B tile)

    for (int k0 = 0; k0 < K; k0 += 8) {
        float4 av = *(const float4*)&Aptr[(size_t)(bm + ar) * K + k0 + ak];
        As[ak + 0][ar] = av.x;
        As[ak + 1][ar] = av.y;
        As[ak + 2][ar] = av.z;
        As[ak + 3][ar] = av.w;
        float4 bv = *(const float4*)&Bin[(size_t)(k0 + bk) * N + bn + bn4];
        *(float4*)&Bs[bk][bn4] = bv;
        __syncthreads();

#pragma unroll
        for (int kk = 0; kk < 8; kk++) {
            float a[8], b[8];
            *(float4*)(a)     = *(const float4*)&As[kk][ty * 8];
            *(float4*)(a + 4) = *(const float4*)&As[kk][ty * 8 + 4];
            *(float4*)(b)     = *(const float4*)&Bs[kk][tx * 8];
            *(float4*)(b + 4) = *(const float4*)&Bs[kk][tx * 8 + 4];
#pragma unroll
            for (int i = 0; i < 8; i++)
#pragma unroll
                for (int j = 0; j < 8; j++)
                    acc[i][j] = fmaf(a[i], b[j], acc[i][j]);
        }
        __syncthreads();
    }

#pragma unroll
    for (int i = 0; i < 8; i++) {
        const int r = bm + ty * 8 + i;
#pragma unroll
        for (int j = 0; j < 8; j++) {
            const int c = bn + tx * 8 + j;
            float v = acc[i][j];
            if (MODE == 1) {
                if (c < DI) g_xin[(size_t)r * DI + c] = v;
                else        g_z  [(size_t)r * DI + (c - DI)] = v;
            } else if (MODE == 2) {
                v += bias[c];
                // softplus = max(v,0) + log1p(exp(-|v|))
                v = fmaxf(v, 0.f) + log1pf(__expf(-fabsf(v)));
                g_dt[(size_t)r * N + c] = v;
            } else {
                C0[(size_t)r * N + c] = v;
            }
        }
    }
}

// ---------------- depthwise causal conv (k=4) + bias + SiLU -------------------
__global__ void __launch_bounds__(256)
conv_kernel(const float* __restrict__ W_conv, const float* __restrict__ b_conv)
{
    const int idx = blockIdx.x * 256 + threadIdx.x;   // over ML*DI
    const int d = idx % DI;
    const int t = idx / DI;      // b*LL + l
    const int l = t % LL;

    float acc = b_conv[d];
#pragma unroll
    for (int j = 0; j < DC; j++) {
        const int ls = l + j - (DC - 1);
        if (ls >= 0)
            acc = fmaf(g_xin[(size_t)(t + j - (DC - 1)) * DI + d], W_conv[d * DC + j], acc);
    }
    const float sig = 1.f / (1.f + __expf(-acc));
    g_xc[idx] = acc * sig;
}

// ---------------- BC = xc @ W_x  (N = 32, split into B | C) -------------------
__global__ void __launch_bounds__(128)
bc_kernel(const float* __restrict__ W_x)
{
    const int row = blockIdx.x * 4 + (threadIdx.x >> 5);  // 0..ML-1
    const int c = threadIdx.x & 31;                       // 0..31
    const float* __restrict__ xr = &g_xc[(size_t)row * DI];
    float acc = 0.f;
#pragma unroll 8
    for (int k = 0; k < DI; k++)
        acc = fmaf(xr[k], W_x[k * (2 * DS) + c], acc);
    if (c < DS) g_Bm[(size_t)row * DS + c]        = acc;
    else        g_Cm[(size_t)row * DS + (c - DS)] = acc;
}

// ---------------- selective scan + skip + z-gate ------------------------------
// One channel (b,d) per 16 lanes; lane n handles state index n.
__global__ void __launch_bounds__(256)
scan_kernel(const float* __restrict__ A_log, const float* __restrict__ Dp)
{
    const int grp = threadIdx.x >> 4;     // 0..15 within block
    const int n   = threadIdx.x & 15;     // state index
    const int ch  = blockIdx.x * 16 + grp;  // 0..BB*DI-1
    const int b   = ch / DI;
    const int d   = ch % DI;

    const float a  = -__expf(A_log[d * DS + n]);
    const float Dv = Dp[d];
    float h = 0.f;
    const int base = b * LL;

    for (int l = 0; l < LL; l++) {
        const int rb = base + l;
        const float dtv = g_dt[(size_t)rb * DI + d];
        const float xcv = g_xc[(size_t)rb * DI + d];
        const float Bn  = g_Bm[(size_t)rb * DS + n];
        const float Cn  = g_Cm[(size_t)rb * DS + n];

        h = fmaf(__expf(dtv * a), h, dtv * Bn * xcv);

        float p = h * Cn;
        p += __shfl_xor_sync(0xffffffffu, p, 8);
        p += __shfl_xor_sync(0xffffffffu, p, 4);
        p += __shfl_xor_sync(0xffffffffu, p, 2);
        p += __shfl_xor_sync(0xffffffffu, p, 1);

        if (n == 0) {
            const float zv  = g_z[(size_t)rb * DI + d];
            const float sig = 1.f / (1.f + __expf(-zv));
            g_y[(size_t)rb * DI + d] = (p + xcv * Dv) * (zv * sig);
        }
    }
}

// ---------------- launch ------------------------------------------------------
extern "C" void kernel_launch(void* const* d_in, const int* in_sizes, int n_in,
                              void* d_out, int out_size)
{
    const float* x      = (const float*)d_in[0];
    const float* W_in   = (const float*)d_in[1];
    const float* W_conv = (const float*)d_in[2];
    const float* b_conv = (const float*)d_in[3];
    const float* W_x    = (const float*)d_in[4];
    const float* W_dt   = (const float*)d_in[5];
    const float* b_dt   = (const float*)d_in[6];
    const float* A_log  = (const float*)d_in[7];
    const float* Dp     = (const float*)d_in[8];
    const float* W_out  = (const float*)d_in[9];
    float* out = (float*)d_out;

    dim3 tpb(16, 16);

    // 1) xz = x @ W_in, split into x_inner / z
    gemm128<1><<<dim3((2 * DI) / 128, ML / 128), tpb>>>(x, W_in, nullptr, nullptr,
                                                        ML, 2 * DI, DM);
    // 2) depthwise causal conv + SiLU
    conv_kernel<<<(ML * DI) / 256, 256>>>(W_conv, b_conv);
    // 3) BC = xc @ W_x
    bc_kernel<<<ML / 4, 128>>>(W_x);
    // 4) dt = softplus(xc @ W_dt + b_dt)
    gemm128<2><<<dim3(DI / 128, ML / 128), tpb>>>(nullptr, W_dt, nullptr, b_dt,
                                                  ML, DI, DI);
    // 5) selective scan + skip + z-gate
    scan_kernel<<<(BB * DI) / 16, 256>>>(A_log, Dp);
    // 6) out = y @ W_out
    gemm128<3><<<dim3(DM / 128, ML / 128), tpb>>>(nullptr, W_out, out, nullptr,
                                                  ML, DM, DI);
}

// round 2
// speedup vs baseline: 2.1808x; 2.1808x over previous
#include <cuda_runtime.h>
#include <cuda_bf16.h>

// Problem constants (fixed by the reference)
#define BB 2
#define LL 2048
#define DM 768
#define DI 1536
#define DS 16
#define DC 4
#define ML (BB*LL)          // 4096 rows

// ---------------- scratch (device globals; no allocs allowed) ----------------
__device__ float g_xin[ML*DI];   // x_inner after W_in split
__device__ float g_z  [ML*DI];   // z gate
__device__ float g_xc [ML*DI];   // conv+silu output
__device__ float g_Bm [ML*DS];   // B matrix
__device__ float g_Cm [ML*DS];   // C matrix
__device__ float g_dt [ML*DI];   // softplus(dt)
__device__ float g_y  [ML*DI];   // scan output, gated

// ---------------- helpers -----------------------------------------------------
__device__ __forceinline__ unsigned f2tf32(float f) {
    unsigned u;
    asm("cvt.rna.tf32.f32 %0, %1;" : "=r"(u) : "f"(f));
    return u;
}

__device__ __forceinline__ void mma_tf32(float& c0, float& c1, float& c2, float& c3,
                                         unsigned a0, unsigned a1, unsigned a2, unsigned a3,
                                         unsigned b0, unsigned b1)
{
    asm volatile(
        "mma.sync.aligned.m16n8k8.row.col.f32.tf32.tf32.f32 "
        "{%0,%1,%2,%3}, {%4,%5,%6,%7}, {%8,%9}, {%0,%1,%2,%3};"
        : "+f"(c0), "+f"(c1), "+f"(c2), "+f"(c3)
        : "r"(a0), "r"(a1), "r"(a2), "r"(a3), "r"(b0), "r"(b1));
}

// ---------------- TF32 tensor-core GEMM, 128x128 tile, BK=16 ------------------
// MODE 1: A = param (x),  B = W_in,  out -> split g_xin / g_z   (N = 2*DI)
// MODE 2: A = g_xc,       B = W_dt,  out -> softplus(.+bias) -> g_dt
// MODE 3: A = g_y,        B = W_out, out -> C0 param (d_out)
template <int MODE>
__global__ void __launch_bounds__(256)
gemm_tf32(const float* __restrict__ Ain, const float* __restrict__ Bin,
          float* __restrict__ C0, const float* __restrict__ bias,
          int M, int N, int K)
{
    const float* __restrict__ A =
        (MODE == 1) ? Ain : (MODE == 2) ? (const float*)g_xc : (const float*)g_y;

    constexpr int BM = 128, BN = 128, BK = 16;
    constexpr int AST = BK + 4;    // 20 floats/row  -> conflict-free frag loads
    constexpr int BST = BN + 8;    // 136 floats/row -> tig*8+gid covers 32 banks

    __shared__ float As[BM * AST];
    __shared__ float Bs[BK * BST];

    const int tid  = threadIdx.x;
    const int lane = tid & 31;
    const int warp = tid >> 5;
    const int gid  = lane >> 2;    // 0..7
    const int tig  = lane & 3;     // 0..3
    const int wm   = (warp >> 2) * 64;   // 0 or 64
    const int wn   = (warp & 3) * 32;    // 0,32,64,96

    const int bm = blockIdx.y * BM;
    const int bn = blockIdx.x * BN;

    // ---- global-load geometry (register prefetch, float4) ----
    // A tile: 128 rows x 16 k -> 512 float4; thread loads f=tid and f=tid+256
    const int arow0 = tid >> 2;            // 0..63
    const int akq   = (tid & 3) * 4;       // 0,4,8,12
    // B tile: 16 k x 128 n -> 512 float4
    const int bk0   = tid >> 5;            // 0..7
    const int bc4   = (tid & 31) * 4;      // 0..124

    const float* aBase = A + (size_t)bm * K;
    const float* bBase = Bin + bn;

    float4 ra0 = *(const float4*)&aBase[(size_t)(arow0)      * K + akq];
    float4 ra1 = *(const float4*)&aBase[(size_t)(arow0 + 64) * K + akq];
    float4 rb0 = *(const float4*)&bBase[(size_t)(bk0)     * N + bc4];
    float4 rb1 = *(const float4*)&bBase[(size_t)(bk0 + 8) * N + bc4];

    float acc[4][4][4];
#pragma unroll
    for (int i = 0; i < 4; i++)
#pragma unroll
        for (int j = 0; j < 4; j++)
#pragma unroll
            for (int q = 0; q < 4; q++) acc[i][j][q] = 0.f;

    for (int kt = 0; kt < K; kt += BK) {
        __syncthreads();
        // store current tiles (tf32-rounded)
        As[(arow0)      * AST + akq + 0] = __uint_as_float(f2tf32(ra0.x));
        As[(arow0)      * AST + akq + 1] = __uint_as_float(f2tf32(ra0.y));
        As[(arow0)      * AST + akq + 2] = __uint_as_float(f2tf32(ra0.z));
        As[(arow0)      * AST + akq + 3] = __uint_as_float(f2tf32(ra0.w));
        As[(arow0 + 64) * AST + akq + 0] = __uint_as_float(f2tf32(ra1.x));
        As[(arow0 + 64) * AST + akq + 1] = __uint_as_float(f2tf32(ra1.y));
        As[(arow0 + 64) * AST + akq + 2] = __uint_as_float(f2tf32(ra1.z));
        As[(arow0 + 64) * AST + akq + 3] = __uint_as_float(f2tf32(ra1.w));
        Bs[(bk0)     * BST + bc4 + 0] = __uint_as_float(f2tf32(rb0.x));
        Bs[(bk0)     * BST + bc4 + 1] = __uint_as_float(f2tf32(rb0.y));
        Bs[(bk0)     * BST + bc4 + 2] = __uint_as_float(f2tf32(rb0.z));
        Bs[(bk0)     * BST + bc4 + 3] = __uint_as_float(f2tf32(rb0.w));
        Bs[(bk0 + 8) * BST + bc4 + 0] = __uint_as_float(f2tf32(rb1.x));
        Bs[(bk0 + 8) * BST + bc4 + 1] = __uint_as_float(f2tf32(rb1.y));
        Bs[(bk0 + 8) * BST + bc4 + 2] = __uint_as_float(f2tf32(rb1.z));
        Bs[(bk0 + 8) * BST + bc4 + 3] = __uint_as_float(f2tf32(rb1.w));
        __syncthreads();

        // prefetch next tile while mmas run
        if (kt + BK < K) {
            const float* aN = aBase + (kt + BK);
            const float* bN = bBase + (size_t)(kt + BK) * N;
            ra0 = *(const float4*)&aN[(size_t)(arow0)      * K + akq];
            ra1 = *(const float4*)&aN[(size_t)(arow0 + 64) * K + akq];
            rb0 = *(const float4*)&bN[(size_t)(bk0)     * N + bc4];
            rb1 = *(const float4*)&bN[(size_t)(bk0 + 8) * N + bc4];
        }

#pragma unroll
        for (int ks = 0; ks < 2; ks++) {
            const int k0 = ks * 8;
            unsigned af[4][4], bf[4][2];
#pragma unroll
            for (int mt = 0; mt < 4; mt++) {
                const int row = wm + mt * 16 + gid;
                af[mt][0] = __float_as_uint(As[(row)     * AST + k0 + tig]);
                af[mt][1] = __float_as_uint(As[(row + 8) * AST + k0 + tig]);
                af[mt][2] = __float_as_uint(As[(row)     * AST + k0 + tig + 4]);
                af[mt][3] = __float_as_uint(As[(row + 8) * AST + k0 + tig + 4]);
            }
#pragma unroll
            for (int nt = 0; nt < 4; nt++) {
                const int col = wn + nt * 8 + gid;
                bf[nt][0] = __float_as_uint(Bs[(k0 + tig)     * BST + col]);
                bf[nt][1] = __float_as_uint(Bs[(k0 + tig + 4) * BST + col]);
            }
#pragma unroll
            for (int mt = 0; mt < 4; mt++)
#pragma unroll
                for (int nt = 0; nt < 4; nt++)
                    mma_tf32(acc[mt][nt][0], acc[mt][nt][1],
                             acc[mt][nt][2], acc[mt][nt][3],
                             af[mt][0], af[mt][1], af[mt][2], af[mt][3],
                             bf[nt][0], bf[nt][1]);
        }
    }

    // ---- epilogue ----
#pragma unroll
    for (int mt = 0; mt < 4; mt++) {
#pragma unroll
        for (int nt = 0; nt < 4; nt++) {
#pragma unroll
            for (int q = 0; q < 4; q++) {
                const int r = bm + wm + mt * 16 + gid + ((q >= 2) ? 8 : 0);
                const int c = bn + wn + nt * 8 + 2 * tig + (q & 1);
                float v = acc[mt][nt][q];
                if (MODE == 1) {
                    if (c < DI) g_xin[(size_t)r * DI + c] = v;
                    else        g_z  [(size_t)r * DI + (c - DI)] = v;
                } else if (MODE == 2) {
                    v += bias[c];
                    v = fmaxf(v, 0.f) + log1pf(__expf(-fabsf(v)));
                    g_dt[(size_t)r * N + c] = v;
                } else {
                    C0[(size_t)r * N + c] = v;
                }
            }
        }
    }
}

// ---------------- depthwise causal conv (k=4) + bias + SiLU -------------------
__global__ void __launch_bounds__(256)
conv_kernel(const float* __restrict__ W_conv, const float* __restrict__ b_conv)
{
    const int idx = blockIdx.x * 256 + threadIdx.x;   // over ML*DI
    const int d = idx % DI;
    const int t = idx / DI;      // b*LL + l
    const int l = t % LL;

    float acc = b_conv[d];
#pragma unroll
    for (int j = 0; j < DC; j++) {
        const int ls = l + j - (DC - 1);
        if (ls >= 0)
            acc = fmaf(g_xin[(size_t)(t + j - (DC - 1)) * DI + d], W_conv[d * DC + j], acc);
    }
    const float sig = 1.f / (1.f + __expf(-acc));
    g_xc[idx] = acc * sig;
}

// ---------------- BC = xc @ W_x  (N = 32, split into B | C) -------------------
// one warp per row; 4 accumulators to break the FMA chain
__global__ void __launch_bounds__(256)
bc_kernel(const float* __restrict__ W_x)
{
    const int row = blockIdx.x * 8 + (threadIdx.x >> 5);
    const int c = threadIdx.x & 31;
    const float* __restrict__ xr = &g_xc[(size_t)row * DI];
    const float* __restrict__ w  = W_x + c;
    float a0 = 0.f, a1 = 0.f, a2 = 0.f, a3 = 0.f;
#pragma unroll 4
    for (int k = 0; k < DI; k += 4) {
        float4 xv = *(const float4*)&xr[k];
        a0 = fmaf(xv.x, w[(k + 0) * 32], a0);
        a1 = fmaf(xv.y, w[(k + 1) * 32], a1);
        a2 = fmaf(xv.z, w[(k + 2) * 32], a2);
        a3 = fmaf(xv.w, w[(k + 3) * 32], a3);
    }
    const float acc = (a0 + a1) + (a2 + a3);
    if (c < DS) g_Bm[(size_t)row * DS + c]        = acc;
    else        g_Cm[(size_t)row * DS + (c - DS)] = acc;
}

// ---------------- selective scan + skip + z-gate ------------------------------
// One channel (b,d) per 16 lanes; lane n handles state index n.
// Next-iteration loads are prefetched so the carried dep is only the h-FMA.
__global__ void __launch_bounds__(128)
scan_kernel(const float* __restrict__ A_log, const float* __restrict__ Dp)
{
    const int grp = threadIdx.x >> 4;       // 0..7 within block
    const int n   = threadIdx.x & 15;       // state index
    const int ch  = blockIdx.x * 8 + grp;   // 0..BB*DI-1
    const int b   = ch / DI;
    const int d   = ch % DI;

    const float a  = -__expf(A_log[d * DS + n]);
    const float Dv = Dp[d];
    float h = 0.f;
    const int base = b * LL;

    // prefetch l = 0
    float dtv = g_dt[(size_t)base * DI + d];
    float xcv = g_xc[(size_t)base * DI + d];
    float Bn  = g_Bm[(size_t)base * DS + n];
    float Cn  = g_Cm[(size_t)base * DS + n];
    float zv  = g_z [(size_t)base * DI + d];

    for (int l = 0; l < LL; l++) {
        const float dt_c = dtv, xc_c = xcv, B_c = Bn, C_c = Cn, z_c = zv;
        if (l + 1 < LL) {
            const int rb = base + l + 1;
            dtv = g_dt[(size_t)rb * DI + d];
            xcv = g_xc[(size_t)rb * DI + d];
            Bn  = g_Bm[(size_t)rb * DS + n];
            Cn  = g_Cm[(size_t)rb * DS + n];
            zv  = g_z [(size_t)rb * DI + d];
        }

        h = fmaf(__expf(dt_c * a), h, dt_c * B_c * xc_c);

        float p = h * C_c;
        p += __shfl_xor_sync(0xffffffffu, p, 8);
        p += __shfl_xor_sync(0xffffffffu, p, 4);
        p += __shfl_xor_sync(0xffffffffu, p, 2);
        p += __shfl_xor_sync(0xffffffffu, p, 1);

        if (n == 0) {
            const float sig = 1.f / (1.f + __expf(-z_c));
            g_y[(size_t)(base + l) * DI + d] = (p + xc_c * Dv) * (z_c * sig);
        }
    }
}

// ---------------- launch ------------------------------------------------------
extern "C" void kernel_launch(void* const* d_in, const int* in_sizes, int n_in,
                              void* d_out, int out_size)
{
    const float* x      = (const float*)d_in[0];
    const float* W_in   = (const float*)d_in[1];
    const float* W_conv = (const float*)d_in[2];
    const float* b_conv = (const float*)d_in[3];
    const float* W_x    = (const float*)d_in[4];
    const float* W_dt   = (const float*)d_in[5];
    const float* b_dt   = (const float*)d_in[6];
    const float* A_log  = (const float*)d_in[7];
    const float* Dp     = (const float*)d_in[8];
    const float* W_out  = (const float*)d_in[9];
    float* out = (float*)d_out;

    // 1) xz = x @ W_in, split into x_inner / z
    gemm_tf32<1><<<dim3((2 * DI) / 128, ML / 128), 256>>>(x, W_in, nullptr, nullptr,
                                                          ML, 2 * DI, DM);
    // 2) depthwise causal conv + SiLU
    conv_kernel<<<(ML * DI) / 256, 256>>>(W_conv, b_conv);
    // 3) BC = xc @ W_x
    bc_kernel<<<ML / 8, 256>>>(W_x);
    // 4) dt = softplus(xc @ W_dt + b_dt)
    gemm_tf32<2><<<dim3(DI / 128, ML / 128), 256>>>(nullptr, W_dt, nullptr, b_dt,
                                                    ML, DI, DI);
    // 5) selective scan + skip + z-gate
    scan_kernel<<<(BB * DI) / 8, 128>>>(A_log, Dp);
    // 6) out = y @ W_out
    gemm_tf32<3><<<dim3(DM / 128, ML / 128), 256>>>(nullptr, W_out, out, nullptr,
                                                    ML, DM, DI);
}

// round 3
// speedup vs baseline: 3.2012x; 1.4679x over previous
#include <cuda_runtime.h>
#include <cuda_bf16.h>

// Problem constants (fixed by the reference)
#define BB 2
#define LL 2048
#define DM 768
#define DI 1536
#define DS 16
#define DC 4
#define ML (BB*LL)          // 4096 rows
#define GSEG 16             // scan segments
#define LC (LL/GSEG)        // 128 steps per segment

// ---------------- scratch (device globals; no allocs allowed) ----------------
__device__ float g_xin[ML*DI];   // x_inner after W_in split
__device__ float g_z  [ML*DI];   // z gate
__device__ float g_xc [ML*DI];   // conv+silu output
__device__ float g_Bm [ML*DS];   // B matrix
__device__ float g_Cm [ML*DS];   // C matrix
__device__ float g_dt [ML*DI];   // softplus(dt)
__device__ float g_y  [ML*DI];   // scan output, gated
// chunked-scan state: index = ((g*BB+b)*DI+d)*DS+n
__device__ float g_h0 [GSEG*BB*DI*DS];
__device__ float g_P  [GSEG*BB*DI*DS];
__device__ float g_hin[GSEG*BB*DI*DS];

// ---------------- helpers -----------------------------------------------------
__device__ __forceinline__ unsigned f2tf32(float f) {
    unsigned u;
    asm("cvt.rna.tf32.f32 %0, %1;" : "=r"(u) : "f"(f));
    return u;
}

__device__ __forceinline__ void mma_tf32(float& c0, float& c1, float& c2, float& c3,
                                         unsigned a0, unsigned a1, unsigned a2, unsigned a3,
                                         unsigned b0, unsigned b1)
{
    asm volatile(
        "mma.sync.aligned.m16n8k8.row.col.f32.tf32.tf32.f32 "
        "{%0,%1,%2,%3}, {%4,%5,%6,%7}, {%8,%9}, {%0,%1,%2,%3};"
        : "+f"(c0), "+f"(c1), "+f"(c2), "+f"(c3)
        : "r"(a0), "r"(a1), "r"(a2), "r"(a3), "r"(b0), "r"(b1));
}

// ---------------- TF32 tensor-core GEMM, 128x128 tile, BK=16, double-buffered -
// MODE 1: A = param (x),  B = W_in,  out -> split g_xin / g_z   (N = 2*DI)
// MODE 2: A = g_xc,       B = W_dt,  out -> softplus(.+bias) -> g_dt
// MODE 3: A = g_y,        B = W_out, out -> C0 param (d_out)
template <int MODE>
__global__ void __launch_bounds__(256)
gemm_tf32(const float* __restrict__ Ain, const float* __restrict__ Bin,
          float* __restrict__ C0, const float* __restrict__ bias,
          int M, int N, int K)
{
    const float* __restrict__ A =
        (MODE == 1) ? Ain : (MODE == 2) ? (const float*)g_xc : (const float*)g_y;

    constexpr int BM = 128, BN = 128, BK = 16;
    constexpr int AST = BK + 4;    // 20 floats/row
    constexpr int BST = BN + 8;    // 136 floats/row

    __shared__ float As[2][BM * AST];
    __shared__ float Bs[2][BK * BST];

    const int tid  = threadIdx.x;
    const int lane = tid & 31;
    const int warp = tid >> 5;
    const int gid  = lane >> 2;    // 0..7
    const int tig  = lane & 3;     // 0..3
    const int wm   = (warp >> 2) * 64;   // 0 or 64
    const int wn   = (warp & 3) * 32;    // 0,32,64,96

    const int bm = blockIdx.y * BM;
    const int bn = blockIdx.x * BN;

    const int arow0 = tid >> 2;            // 0..63
    const int akq   = (tid & 3) * 4;       // 0,4,8,12
    const int bk0   = tid >> 5;            // 0..7
    const int bc4   = (tid & 31) * 4;      // 0..124

    const float* aBase = A + (size_t)bm * K;
    const float* bBase = Bin + bn;

    float4 ra0, ra1, rb0, rb1;
    // load tile 0
    ra0 = *(const float4*)&aBase[(size_t)(arow0)      * K + akq];
    ra1 = *(const float4*)&aBase[(size_t)(arow0 + 64) * K + akq];
    rb0 = *(const float4*)&bBase[(size_t)(bk0)     * N + bc4];
    rb1 = *(const float4*)&bBase[(size_t)(bk0 + 8) * N + bc4];

    float acc[4][4][4];
#pragma unroll
    for (int i = 0; i < 4; i++)
#pragma unroll
        for (int j = 0; j < 4; j++)
#pragma unroll
            for (int q = 0; q < 4; q++) acc[i][j][q] = 0.f;

    // store tile 0 into buffer 0
    {
        float* as = As[0]; float* bs = Bs[0];
        as[(arow0)      * AST + akq + 0] = __uint_as_float(f2tf32(ra0.x));
        as[(arow0)      * AST + akq + 1] = __uint_as_float(f2tf32(ra0.y));
        as[(arow0)      * AST + akq + 2] = __uint_as_float(f2tf32(ra0.z));
        as[(arow0)      * AST + akq + 3] = __uint_as_float(f2tf32(ra0.w));
        as[(arow0 + 64) * AST + akq + 0] = __uint_as_float(f2tf32(ra1.x));
        as[(arow0 + 64) * AST + akq + 1] = __uint_as_float(f2tf32(ra1.y));
        as[(arow0 + 64) * AST + akq + 2] = __uint_as_float(f2tf32(ra1.z));
        as[(arow0 + 64) * AST + akq + 3] = __uint_as_float(f2tf32(ra1.w));
        bs[(bk0)     * BST + bc4 + 0] = __uint_as_float(f2tf32(rb0.x));
        bs[(bk0)     * BST + bc4 + 1] = __uint_as_float(f2tf32(rb0.y));
        bs[(bk0)     * BST + bc4 + 2] = __uint_as_float(f2tf32(rb0.z));
        bs[(bk0)     * BST + bc4 + 3] = __uint_as_float(f2tf32(rb0.w));
        bs[(bk0 + 8) * BST + bc4 + 0] = __uint_as_float(f2tf32(rb1.x));
        bs[(bk0 + 8) * BST + bc4 + 1] = __uint_as_float(f2tf32(rb1.y));
        bs[(bk0 + 8) * BST + bc4 + 2] = __uint_as_float(f2tf32(rb1.z));
        bs[(bk0 + 8) * BST + bc4 + 3] = __uint_as_float(f2tf32(rb1.w));
    }
    __syncthreads();

    int buf = 0;
    for (int kt = 0; kt < K; kt += BK) {
        const bool more = (kt + BK < K);
        if (more) {
            const float* aN = aBase + (kt + BK);
            const float* bN = bBase + (size_t)(kt + BK) * N;
            ra0 = *(const float4*)&aN[(size_t)(arow0)      * K + akq];
            ra1 = *(const float4*)&aN[(size_t)(arow0 + 64) * K + akq];
            rb0 = *(const float4*)&bN[(size_t)(bk0)     * N + bc4];
            rb1 = *(const float4*)&bN[(size_t)(bk0 + 8) * N + bc4];
        }

        const float* as = As[buf];
        const float* bs = Bs[buf];
#pragma unroll
        for (int ks = 0; ks < 2; ks++) {
            const int k0 = ks * 8;
            unsigned af[4][4], bf[4][2];
#pragma unroll
            for (int mt = 0; mt < 4; mt++) {
                const int row = wm + mt * 16 + gid;
                af[mt][0] = __float_as_uint(as[(row)     * AST + k0 + tig]);
                af[mt][1] = __float_as_uint(as[(row + 8) * AST + k0 + tig]);
                af[mt][2] = __float_as_uint(as[(row)     * AST + k0 + tig + 4]);
                af[mt][3] = __float_as_uint(as[(row + 8) * AST + k0 + tig + 4]);
            }
#pragma unroll
            for (int nt = 0; nt < 4; nt++) {
                const int col = wn + nt * 8 + gid;
                bf[nt][0] = __float_as_uint(bs[(k0 + tig)     * BST + col]);
                bf[nt][1] = __float_as_uint(bs[(k0 + tig + 4) * BST + col]);
            }
#pragma unroll
            for (int mt = 0; mt < 4; mt++)
#pragma unroll
                for (int nt = 0; nt < 4; nt++)
                    mma_tf32(acc[mt][nt][0], acc[mt][nt][1],
                             acc[mt][nt][2], acc[mt][nt][3],
                             af[mt][0], af[mt][1], af[mt][2], af[mt][3],
                             bf[nt][0], bf[nt][1]);
        }

        if (more) {
            float* asn = As[buf ^ 1]; float* bsn = Bs[buf ^ 1];
            asn[(arow0)      * AST + akq + 0] = __uint_as_float(f2tf32(ra0.x));
            asn[(arow0)      * AST + akq + 1] = __uint_as_float(f2tf32(ra0.y));
            asn[(arow0)      * AST + akq + 2] = __uint_as_float(f2tf32(ra0.z));
            asn[(arow0)      * AST + akq + 3] = __uint_as_float(f2tf32(ra0.w));
            asn[(arow0 + 64) * AST + akq + 0] = __uint_as_float(f2tf32(ra1.x));
            asn[(arow0 + 64) * AST + akq + 1] = __uint_as_float(f2tf32(ra1.y));
            asn[(arow0 + 64) * AST + akq + 2] = __uint_as_float(f2tf32(ra1.z));
            asn[(arow0 + 64) * AST + akq + 3] = __uint_as_float(f2tf32(ra1.w));
            bsn[(bk0)     * BST + bc4 + 0] = __uint_as_float(f2tf32(rb0.x));
            bsn[(bk0)     * BST + bc4 + 1] = __uint_as_float(f2tf32(rb0.y));
            bsn[(bk0)     * BST + bc4 + 2] = __uint_as_float(f2tf32(rb0.z));
            bsn[(bk0)     * BST + bc4 + 3] = __uint_as_float(f2tf32(rb0.w));
            bsn[(bk0 + 8) * BST + bc4 + 0] = __uint_as_float(f2tf32(rb1.x));
            bsn[(bk0 + 8) * BST + bc4 + 1] = __uint_as_float(f2tf32(rb1.y));
            bsn[(bk0 + 8) * BST + bc4 + 2] = __uint_as_float(f2tf32(rb1.z));
            bsn[(bk0 + 8) * BST + bc4 + 3] = __uint_as_float(f2tf32(rb1.w));
            __syncthreads();
            buf ^= 1;
        }
    }

    // ---- epilogue ----
#pragma unroll
    for (int mt = 0; mt < 4; mt++) {
#pragma unroll
        for (int nt = 0; nt < 4; nt++) {
#pragma unroll
            for (int q = 0; q < 4; q++) {
                const int r = bm + wm + mt * 16 + gid + ((q >= 2) ? 8 : 0);
                const int c = bn + wn + nt * 8 + 2 * tig + (q & 1);
                float v = acc[mt][nt][q];
                if (MODE == 1) {
                    if (c < DI) g_xin[(size_t)r * DI + c] = v;
                    else        g_z  [(size_t)r * DI + (c - DI)] = v;
                } else if (MODE == 2) {
                    v += bias[c];
                    v = fmaxf(v, 0.f) + log1pf(__expf(-fabsf(v)));
                    g_dt[(size_t)r * N + c] = v;
                } else {
                    C0[(size_t)r * N + c] = v;
                }
            }
        }
    }
}

// ---------------- depthwise causal conv (k=4) + bias + SiLU -------------------
__global__ void __launch_bounds__(256)
conv_kernel(const float* __restrict__ W_conv, const float* __restrict__ b_conv)
{
    const int idx = blockIdx.x * 256 + threadIdx.x;   // over ML*DI
    const int d = idx % DI;
    const int t = idx / DI;      // b*LL + l
    const int l = t % LL;

    float acc = b_conv[d];
#pragma unroll
    for (int j = 0; j < DC; j++) {
        const int ls = l + j - (DC - 1);
        if (ls >= 0)
            acc = fmaf(g_xin[(size_t)(t + j - (DC - 1)) * DI + d], W_conv[d * DC + j], acc);
    }
    const float sig = 1.f / (1.f + __expf(-acc));
    g_xc[idx] = acc * sig;
}

// ---------------- BC = xc @ W_x  (N = 32) — 4 rows per warp -------------------
__global__ void __launch_bounds__(256)
bc_kernel(const float* __restrict__ W_x)
{
    const int warp = threadIdx.x >> 5;
    const int c = threadIdx.x & 31;
    const int row = (blockIdx.x * 8 + warp) * 4;
    const float* __restrict__ w = W_x + c;
    float a0 = 0.f, a1 = 0.f, a2 = 0.f, a3 = 0.f;
#pragma unroll 2
    for (int k = 0; k < DI; k += 4) {
        const float w0 = w[(k + 0) * 32];
        const float w1 = w[(k + 1) * 32];
        const float w2 = w[(k + 2) * 32];
        const float w3 = w[(k + 3) * 32];
        float4 x0 = *(const float4*)&g_xc[(size_t)(row + 0) * DI + k];
        float4 x1 = *(const float4*)&g_xc[(size_t)(row + 1) * DI + k];
        float4 x2 = *(const float4*)&g_xc[(size_t)(row + 2) * DI + k];
        float4 x3 = *(const float4*)&g_xc[(size_t)(row + 3) * DI + k];
        a0 = fmaf(x0.x, w0, fmaf(x0.y, w1, fmaf(x0.z, w2, fmaf(x0.w, w3, a0))));
        a1 = fmaf(x1.x, w0, fmaf(x1.y, w1, fmaf(x1.z, w2, fmaf(x1.w, w3, a1))));
        a2 = fmaf(x2.x, w0, fmaf(x2.y, w1, fmaf(x2.z, w2, fmaf(x2.w, w3, a2))));
        a3 = fmaf(x3.x, w0, fmaf(x3.y, w1, fmaf(x3.z, w2, fmaf(x3.w, w3, a3))));
    }
    float acc4[4] = {a0, a1, a2, a3};
#pragma unroll
    for (int r = 0; r < 4; r++) {
        if (c < DS) g_Bm[(size_t)(row + r) * DS + c]        = acc4[r];
        else        g_Cm[(size_t)(row + r) * DS + (c - DS)] = acc4[r];
    }
}

// ---------------- chunked selective scan --------------------------------------
// Segment index space: idx = (g*BB + b)*DI + d, lane n = state.
// Phase A: zero-init scan per segment -> h_end0, P = exp(a * sum(dt))
__global__ void __launch_bounds__(128)
scanA_kernel(const float* __restrict__ A_log)
{
    const int grp = threadIdx.x >> 4;
    const int n   = threadIdx.x & 15;
    const int idx = blockIdx.x * 8 + grp;    // (g*BB+b)*DI + d
    const int d   = idx % DI;
    const int t   = idx / DI;
    const int b   = t % BB;
    const int g   = t / BB;

    const float a = -__expf(A_log[d * DS + n]);
    float h = 0.f, sdt = 0.f;
    const int base = b * LL + g * LC;

    float dtv = g_dt[(size_t)base * DI + d];
    float xcv = g_xc[(size_t)base * DI + d];
    float Bn  = g_Bm[(size_t)base * DS + n];

    for (int i = 0; i < LC; i++) {
        const float dt_c = dtv, xc_c = xcv, B_c = Bn;
        if (i + 1 < LC) {
            const int rb = base + i + 1;
            dtv = g_dt[(size_t)rb * DI + d];
            xcv = g_xc[(size_t)rb * DI + d];
            Bn  = g_Bm[(size_t)rb * DS + n];
        }
        h = fmaf(__expf(dt_c * a), h, dt_c * B_c * xc_c);
        sdt += dt_c;
    }
    g_h0[(size_t)idx * DS + n] = h;
    g_P [(size_t)idx * DS + n] = __expf(a * sdt);
}

// Phase B: splice segments sequentially (tiny)
__global__ void __launch_bounds__(256)
scanB_kernel()
{
    const int i = blockIdx.x * 256 + threadIdx.x;   // over BB*DI*DS
    const int n = i & 15;
    const int r = i >> 4;        // b*DI + d
    const int d = r % DI;
    const int b = r / DI;

    float h = 0.f;
#pragma unroll
    for (int g = 0; g < GSEG; g++) {
        const size_t j = (size_t)(((g * BB + b) * DI) + d) * DS + n;
        g_hin[j] = h;
        h = fmaf(g_P[j], h, g_h0[j]);
    }
}

// Phase C: full scan per segment from correct h_in, produce gated y
__global__ void __launch_bounds__(128)
scanC_kernel(const float* __restrict__ A_log, const float* __restrict__ Dp)
{
    const int grp = threadIdx.x >> 4;
    const int n   = threadIdx.x & 15;
    const int idx = blockIdx.x * 8 + grp;
    const int d   = idx % DI;
    const int t   = idx / DI;
    const int b   = t % BB;
    const int g   = t / BB;

    const float a  = -__expf(A_log[d * DS + n]);
    const float Dv = Dp[d];
    float h = g_hin[(size_t)idx * DS + n];
    const int base = b * LL + g * LC;

    float dtv = g_dt[(size_t)base * DI + d];
    float xcv = g_xc[(size_t)base * DI + d];
    float Bn  = g_Bm[(size_t)base * DS + n];
    float Cn  = g_Cm[(size_t)base * DS + n];
    float zv  = g_z [(size_t)base * DI + d];

    for (int i = 0; i < LC; i++) {
        const float dt_c = dtv, xc_c = xcv, B_c = Bn, C_c = Cn, z_c = zv;
        if (i + 1 < LC) {
            const int rb = base + i + 1;
            dtv = g_dt[(size_t)rb * DI + d];
            xcv = g_xc[(size_t)rb * DI + d];
            Bn  = g_Bm[(size_t)rb * DS + n];
            Cn  = g_Cm[(size_t)rb * DS + n];
            zv  = g_z [(size_t)rb * DI + d];
        }

        h = fmaf(__expf(dt_c * a), h, dt_c * B_c * xc_c);

        float p = h * C_c;
        p += __shfl_xor_sync(0xffffffffu, p, 8);
        p += __shfl_xor_sync(0xffffffffu, p, 4);
        p += __shfl_xor_sync(0xffffffffu, p, 2);
        p += __shfl_xor_sync(0xffffffffu, p, 1);

        if (n == 0) {
            const float sig = 1.f / (1.f + __expf(-z_c));
            g_y[(size_t)(base + i) * DI + d] = (p + xc_c * Dv) * (z_c * sig);
        }
    }
}

// ---------------- launch ------------------------------------------------------
extern "C" void kernel_launch(void* const* d_in, const int* in_sizes, int n_in,
                              void* d_out, int out_size)
{
    const float* x      = (const float*)d_in[0];
    const float* W_in   = (const float*)d_in[1];
    const float* W_conv = (const float*)d_in[2];
    const float* b_conv = (const float*)d_in[3];
    const float* W_x    = (const float*)d_in[4];
    const float* W_dt   = (const float*)d_in[5];
    const float* b_dt   = (const float*)d_in[6];
    const float* A_log  = (const float*)d_in[7];
    const float* Dp     = (const float*)d_in[8];
    const float* W_out  = (const float*)d_in[9];
    float* out = (float*)d_out;

    // 1) xz = x @ W_in, split into x_inner / z
    gemm_tf32<1><<<dim3((2 * DI) / 128, ML / 128), 256>>>(x, W_in, nullptr, nullptr,
                                                          ML, 2 * DI, DM);
    // 2) depthwise causal conv + SiLU
    conv_kernel<<<(ML * DI) / 256, 256>>>(W_conv, b_conv);
    // 3) BC = xc @ W_x
    bc_kernel<<<ML / 32, 256>>>(W_x);
    // 4) dt = softplus(xc @ W_dt + b_dt)
    gemm_tf32<2><<<dim3(DI / 128, ML / 128), 256>>>(nullptr, W_dt, nullptr, b_dt,
                                                    ML, DI, DI);
    // 5) chunked selective scan
    scanA_kernel<<<(GSEG * BB * DI) / 8, 128>>>(A_log);
    scanB_kernel<<<(BB * DI * DS) / 256, 256>>>();
    scanC_kernel<<<(GSEG * BB * DI) / 8, 128>>>(A_log, Dp);
    // 6) out = y @ W_out
    gemm_tf32<3><<<dim3(DM / 128, ML / 128), 256>>>(nullptr, W_out, out, nullptr,
                                                    ML, DM, DI);
}

// round 4
// speedup vs baseline: 3.2064x; 1.0016x over previous
#include <cuda_runtime.h>
#include <cuda_bf16.h>

// Problem constants (fixed by the reference)
#define BB 2
#define LL 2048
#define DM 768
#define DI 1536
#define DS 16
#define DC 4
#define ML (BB*LL)          // 4096 rows
#define GSEG 16             // scan segments
#define LC (LL/GSEG)        // 128 steps per segment

// ---------------- scratch (device globals; no allocs allowed) ----------------
__device__ float g_xin[ML*DI];   // x_inner after W_in split
__device__ float g_z  [ML*DI];   // z gate
__device__ float g_xc [ML*DI];   // conv+silu output (exact)
__device__ float g_Bm [ML*DS];
__device__ float g_Cm [ML*DS];
__device__ float g_dt [ML*DI];
__device__ float g_y  [ML*DI];   // scan output, gated (tf32-rounded)
__device__ float g_h0 [GSEG*BB*DI*DS];
__device__ float g_P  [GSEG*BB*DI*DS];
__device__ float g_hin[GSEG*BB*DI*DS];
// tf32-prerounded operands
__device__ float g_xtf   [ML*DM];
__device__ float g_xctf  [ML*DI];
__device__ float g_wintf [DM*2*DI];
__device__ float g_wdttf [DI*DI];
__device__ float g_wouttf[DI*DM];

// ---------------- helpers -----------------------------------------------------
__device__ __forceinline__ unsigned f2tf32(float f) {
    unsigned u;
    asm("cvt.rna.tf32.f32 %0, %1;" : "=r"(u) : "f"(f));
    return u;
}
__device__ __forceinline__ float rtf(float f) { return __uint_as_float(f2tf32(f)); }

__device__ __forceinline__ void mma_tf32(float& c0, float& c1, float& c2, float& c3,
                                         unsigned a0, unsigned a1, unsigned a2, unsigned a3,
                                         unsigned b0, unsigned b1)
{
    asm volatile(
        "mma.sync.aligned.m16n8k8.row.col.f32.tf32.tf32.f32 "
        "{%0,%1,%2,%3}, {%4,%5,%6,%7}, {%8,%9}, {%0,%1,%2,%3};"
        : "+f"(c0), "+f"(c1), "+f"(c2), "+f"(c3)
        : "r"(a0), "r"(a1), "r"(a2), "r"(a3), "r"(b0), "r"(b1));
}

// ---------------- pre-round to tf32 -------------------------------------------
// ID: 0 -> g_xtf, 1 -> g_wintf, 2 -> g_wdttf, 3 -> g_wouttf
template <int ID>
__global__ void __launch_bounds__(256)
round_k(const float* __restrict__ src)
{
    float* dst = (ID == 0) ? g_xtf : (ID == 1) ? g_wintf
               : (ID == 2) ? g_wdttf : g_wouttf;
    const int i = (blockIdx.x * 256 + threadIdx.x) * 4;
    float4 v = *(const float4*)&src[i];
    v.x = rtf(v.x); v.y = rtf(v.y); v.z = rtf(v.z); v.w = rtf(v.w);
    *(float4*)&dst[i] = v;
}

// ---------------- TF32 tensor-core GEMM, fragment-native smem layout ----------
// 128x128 tile, BK=16, double-buffered.
// MODE 1: A=g_xtf,  B=g_wintf,  out -> split g_xin / g_z   (N = 2*DI)
// MODE 2: A=g_xctf, B=g_wdttf,  out -> softplus(.+bias) -> g_dt
// MODE 3: A=g_y,    B=g_wouttf, out -> C0 param (d_out)
//
// A smem layout (per buffer, 2048 floats):
//   idxA(ks,rb,gid,tig) = (((ks*8+rb)*8+gid)*4+tig)*4, components +0..3 =
//   (row=rb*16+gid + 8*rh, k = ks*8 + 4*half + tig) with comp = rh + 2*half.
// B smem layout (per buffer, 2112 floats, 2-float pad per cb group):
//   idxB(ks,cb,cg,tig) = ks*1056 + cb*66 + (cg*4+tig)*2, components +0/+1 =
//   (k = ks*8 + 4*half + tig, col = cb*8+cg), comp = half.
template <int MODE>
__global__ void __launch_bounds__(256)
gemm_tf32(float* __restrict__ C0, const float* __restrict__ bias,
          int M, int N, int K)
{
    const float* __restrict__ A =
        (MODE == 1) ? (const float*)g_xtf : (MODE == 2) ? (const float*)g_xctf
                                                        : (const float*)g_y;
    const float* __restrict__ B =
        (MODE == 1) ? (const float*)g_wintf : (MODE == 2) ? (const float*)g_wdttf
                                                          : (const float*)g_wouttf;

    constexpr int BM = 128, BK = 16;
    __shared__ float As[2][2048];
    __shared__ float Bs[2][2112];

    const int tid  = threadIdx.x;
    const int lane = tid & 31;
    const int warp = tid >> 5;
    const int gid  = lane >> 2;    // 0..7
    const int tig  = lane & 3;     // 0..3
    const int wm   = (warp >> 2) * 64;   // 0 or 64
    const int wn   = (warp & 3) * 32;    // 0,32,64,96

    const int bm = blockIdx.y * BM;
    const int bn = blockIdx.x * 128;

    // ---- A global-load geometry: rows r1, r1+8 ; k = akq..akq+3 ----
    const int arow = tid >> 2;                    // 0..63
    const int r1   = ((arow >> 3) << 4) + (arow & 7);   // covers all 128 rows with r1, r1+8
    const int akq  = (tid & 3) * 4;               // 0,4,8,12
    const int aks  = akq >> 3;
    const int ahalf = (akq >> 2) & 1;
    const int asto = ((((aks * 8 + (r1 >> 4)) * 8 + (r1 & 7)) * 4) * 4) + 2 * ahalf;
    // per j (tig): asto + j*4

    // ---- B global-load geometry: k pair (k1, k1+4); cols bc4..bc4+3 ----
    const int bq   = tid >> 5;                    // 0..7
    const int k1   = (bq & 3) + ((bq >> 2) << 3); // {0..3, 8..11}
    const int bks  = bq >> 2;
    const int btig = bq & 3;
    const int bc4  = (tid & 31) * 4;              // 0..124

    const float* aBase = A + (size_t)bm * K;
    const float* bBase = B + bn;

    float4 ra1v, ra2v, rb1v, rb2v;
    ra1v = *(const float4*)&aBase[(size_t)(r1)     * K + akq];
    ra2v = *(const float4*)&aBase[(size_t)(r1 + 8) * K + akq];
    rb1v = *(const float4*)&bBase[(size_t)(k1)     * N + bc4];
    rb2v = *(const float4*)&bBase[(size_t)(k1 + 4) * N + bc4];

    float acc[4][4][4];
#pragma unroll
    for (int i = 0; i < 4; i++)
#pragma unroll
        for (int j = 0; j < 4; j++)
#pragma unroll
            for (int q = 0; q < 4; q++) acc[i][j][q] = 0.f;

    // store tile 0 into buffer 0
    {
        float* as = As[0]; float* bs = Bs[0];
        const float a1[4] = {ra1v.x, ra1v.y, ra1v.z, ra1v.w};
        const float a2[4] = {ra2v.x, ra2v.y, ra2v.z, ra2v.w};
#pragma unroll
        for (int j = 0; j < 4; j++)
            *(float2*)&as[asto + j * 4] = make_float2(a1[j], a2[j]);
        const float b1[4] = {rb1v.x, rb1v.y, rb1v.z, rb1v.w};
        const float b2[4] = {rb2v.x, rb2v.y, rb2v.z, rb2v.w};
#pragma unroll
        for (int j = 0; j < 4; j++) {
            const int col = bc4 + j;
            const int idx = bks * 1056 + (col >> 3) * 66 + ((col & 7) * 4 + btig) * 2;
            *(float2*)&bs[idx] = make_float2(b1[j], b2[j]);
        }
    }
    __syncthreads();

    int buf = 0;
    for (int kt = 0; kt < K; kt += BK) {
        const bool more = (kt + BK < K);
        if (more) {
            const float* aN = aBase + (kt + BK);
            const float* bN = bBase + (size_t)(kt + BK) * N;
            ra1v = *(const float4*)&aN[(size_t)(r1)     * K + akq];
            ra2v = *(const float4*)&aN[(size_t)(r1 + 8) * K + akq];
            rb1v = *(const float4*)&bN[(size_t)(k1)     * N + bc4];
            rb2v = *(const float4*)&bN[(size_t)(k1 + 4) * N + bc4];
        }

        const float* as = As[buf];
        const float* bs = Bs[buf];
#pragma unroll
        for (int ks = 0; ks < 2; ks++) {
            float4 af[4];
            float2 bf[4];
#pragma unroll
            for (int mt = 0; mt < 4; mt++)
                af[mt] = *(const float4*)&as[(((ks * 8 + (wm >> 4) + mt) * 8 + gid) * 4 + tig) * 4];
#pragma unroll
            for (int nt = 0; nt < 4; nt++)
                bf[nt] = *(const float2*)&bs[ks * 1056 + ((wn >> 3) + nt) * 66 + (gid * 4 + tig) * 2];
#pragma unroll
            for (int mt = 0; mt < 4; mt++)
#pragma unroll
                for (int nt = 0; nt < 4; nt++)
                    mma_tf32(acc[mt][nt][0], acc[mt][nt][1],
                             acc[mt][nt][2], acc[mt][nt][3],
                             __float_as_uint(af[mt].x), __float_as_uint(af[mt].y),
                             __float_as_uint(af[mt].z), __float_as_uint(af[mt].w),
                             __float_as_uint(bf[nt].x), __float_as_uint(bf[nt].y));
        }

        if (more) {
            float* asn = As[buf ^ 1]; float* bsn = Bs[buf ^ 1];
            const float a1[4] = {ra1v.x, ra1v.y, ra1v.z, ra1v.w};
            const float a2[4] = {ra2v.x, ra2v.y, ra2v.z, ra2v.w};
#pragma unroll
            for (int j = 0; j < 4; j++)
                *(float2*)&asn[asto + j * 4] = make_float2(a1[j], a2[j]);
            const float b1[4] = {rb1v.x, rb1v.y, rb1v.z, rb1v.w};
            const float b2[4] = {rb2v.x, rb2v.y, rb2v.z, rb2v.w};
#pragma unroll
            for (int j = 0; j < 4; j++) {
                const int col = bc4 + j;
                const int idx = bks * 1056 + (col >> 3) * 66 + ((col & 7) * 4 + btig) * 2;
                *(float2*)&bsn[idx] = make_float2(b1[j], b2[j]);
            }
            __syncthreads();
            buf ^= 1;
        }
    }

    // ---- epilogue ----
#pragma unroll
    for (int mt = 0; mt < 4; mt++) {
#pragma unroll
        for (int nt = 0; nt < 4; nt++) {
#pragma unroll
            for (int q = 0; q < 4; q++) {
                const int r = bm + wm + mt * 16 + gid + ((q >= 2) ? 8 : 0);
                const int c = bn + wn + nt * 8 + 2 * tig + (q & 1);
                float v = acc[mt][nt][q];
                if (MODE == 1) {
                    if (c < DI) g_xin[(size_t)r * DI + c] = v;
                    else        g_z  [(size_t)r * DI + (c - DI)] = v;
                } else if (MODE == 2) {
                    v += bias[c];
                    v = fmaxf(v, 0.f) + log1pf(__expf(-fabsf(v)));
                    g_dt[(size_t)r * N + c] = v;
                } else {
                    C0[(size_t)r * N + c] = v;
                }
            }
        }
    }
}

// ---------------- depthwise causal conv (k=4) + bias + SiLU -------------------
__global__ void __launch_bounds__(256)
conv_kernel(const float* __restrict__ W_conv, const float* __restrict__ b_conv)
{
    const int idx = blockIdx.x * 256 + threadIdx.x;   // over ML*DI
    const int d = idx % DI;
    const int t = idx / DI;      // b*LL + l
    const int l = t % LL;

    float acc = b_conv[d];
#pragma unroll
    for (int j = 0; j < DC; j++) {
        const int ls = l + j - (DC - 1);
        if (ls >= 0)
            acc = fmaf(g_xin[(size_t)(t + j - (DC - 1)) * DI + d], W_conv[d * DC + j], acc);
    }
    const float sig = 1.f / (1.f + __expf(-acc));
    const float v = acc * sig;
    g_xc[idx]   = v;
    g_xctf[idx] = rtf(v);
}

// ---------------- BC = xc @ W_x  (N = 32) — 4 rows per warp -------------------
__global__ void __launch_bounds__(256)
bc_kernel(const float* __restrict__ W_x)
{
    const int warp = threadIdx.x >> 5;
    const int c = threadIdx.x & 31;
    const int row = (blockIdx.x * 8 + warp) * 4;
    const float* __restrict__ w = W_x + c;
    float a0 = 0.f, a1 = 0.f, a2 = 0.f, a3 = 0.f;
#pragma unroll 2
    for (int k = 0; k < DI; k += 4) {
        const float w0 = w[(k + 0) * 32];
        const float w1 = w[(k + 1) * 32];
        const float w2 = w[(k + 2) * 32];
        const float w3 = w[(k + 3) * 32];
        float4 x0 = *(const float4*)&g_xc[(size_t)(row + 0) * DI + k];
        float4 x1 = *(const float4*)&g_xc[(size_t)(row + 1) * DI + k];
        float4 x2 = *(const float4*)&g_xc[(size_t)(row + 2) * DI + k];
        float4 x3 = *(const float4*)&g_xc[(size_t)(row + 3) * DI + k];
        a0 = fmaf(x0.x, w0, fmaf(x0.y, w1, fmaf(x0.z, w2, fmaf(x0.w, w3, a0))));
        a1 = fmaf(x1.x, w0, fmaf(x1.y, w1, fmaf(x1.z, w2, fmaf(x1.w, w3, a1))));
        a2 = fmaf(x2.x, w0, fmaf(x2.y, w1, fmaf(x2.z, w2, fmaf(x2.w, w3, a2))));
        a3 = fmaf(x3.x, w0, fmaf(x3.y, w1, fmaf(x3.z, w2, fmaf(x3.w, w3, a3))));
    }
    float acc4[4] = {a0, a1, a2, a3};
#pragma unroll
    for (int r = 0; r < 4; r++) {
        if (c < DS) g_Bm[(size_t)(row + r) * DS + c]        = acc4[r];
        else        g_Cm[(size_t)(row + r) * DS + (c - DS)] = acc4[r];
    }
}

// ---------------- chunked selective scan --------------------------------------
__global__ void __launch_bounds__(128)
scanA_kernel(const float* __restrict__ A_log)
{
    const int grp = threadIdx.x >> 4;
    const int n   = threadIdx.x & 15;
    const int idx = blockIdx.x * 8 + grp;    // (g*BB+b)*DI + d
    const int d   = idx % DI;
    const int t   = idx / DI;
    const int b   = t % BB;
    const int g   = t / BB;

    const float a = -__expf(A_log[d * DS + n]);
    float h = 0.f, sdt = 0.f;
    const int base = b * LL + g * LC;

    float dtv = g_dt[(size_t)base * DI + d];
    float xcv = g_xc[(size_t)base * DI + d];
    float Bn  = g_Bm[(size_t)base * DS + n];

    for (int i = 0; i < LC; i++) {
        const float dt_c = dtv, xc_c = xcv, B_c = Bn;
        if (i + 1 < LC) {
            const int rb = base + i + 1;
            dtv = g_dt[(size_t)rb * DI + d];
            xcv = g_xc[(size_t)rb * DI + d];
            Bn  = g_Bm[(size_t)rb * DS + n];
        }
        h = fmaf(__expf(dt_c * a), h, dt_c * B_c * xc_c);
        sdt += dt_c;
    }
    g_h0[(size_t)idx * DS + n] = h;
    g_P [(size_t)idx * DS + n] = __expf(a * sdt);
}

__global__ void __launch_bounds__(256)
scanB_kernel()
{
    const int i = blockIdx.x * 256 + threadIdx.x;   // over BB*DI*DS
    const int n = i & 15;
    const int r = i >> 4;        // b*DI + d
    const int d = r % DI;
    const int b = r / DI;

    float h = 0.f;
#pragma unroll
    for (int g = 0; g < GSEG; g++) {
        const size_t j = (size_t)(((g * BB + b) * DI) + d) * DS + n;
        g_hin[j] = h;
        h = fmaf(g_P[j], h, g_h0[j]);
    }
}

__global__ void __launch_bounds__(128)
scanC_kernel(const float* __restrict__ A_log, const float* __restrict__ Dp)
{
    const int grp = threadIdx.x >> 4;
    const int n   = threadIdx.x & 15;
    const int idx = blockIdx.x * 8 + grp;
    const int d   = idx % DI;
    const int t   = idx / DI;
    const int b   = t % BB;
    const int g   = t / BB;

    const float a  = -__expf(A_log[d * DS + n]);
    const float Dv = Dp[d];
    float h = g_hin[(size_t)idx * DS + n];
    const int base = b * LL + g * LC;

    float dtv = g_dt[(size_t)base * DI + d];
    float xcv = g_xc[(size_t)base * DI + d];
    float Bn  = g_Bm[(size_t)base * DS + n];
    float Cn  = g_Cm[(size_t)base * DS + n];
    float zv  = g_z [(size_t)base * DI + d];

    for (int i = 0; i < LC; i++) {
        const float dt_c = dtv, xc_c = xcv, B_c = Bn, C_c = Cn, z_c = zv;
        if (i + 1 < LC) {
            const int rb = base + i + 1;
            dtv = g_dt[(size_t)rb * DI + d];
            xcv = g_xc[(size_t)rb * DI + d];
            Bn  = g_Bm[(size_t)rb * DS + n];
            Cn  = g_Cm[(size_t)rb * DS + n];
            zv  = g_z [(size_t)rb * DI + d];
        }

        h = fmaf(__expf(dt_c * a), h, dt_c * B_c * xc_c);

        float p = h * C_c;
        p += __shfl_xor_sync(0xffffffffu, p, 8);
        p += __shfl_xor_sync(0xffffffffu, p, 4);
        p += __shfl_xor_sync(0xffffffffu, p, 2);
        p += __shfl_xor_sync(0xffffffffu, p, 1);

        if (n == 0) {
            const float sig = 1.f / (1.f + __expf(-z_c));
            g_y[(size_t)(base + i) * DI + d] = rtf((p + xc_c * Dv) * (z_c * sig));
        }
    }
}

// ---------------- launch ------------------------------------------------------
extern "C" void kernel_launch(void* const* d_in, const int* in_sizes, int n_in,
                              void* d_out, int out_size)
{
    const float* x      = (const float*)d_in[0];
    const float* W_in   = (const float*)d_in[1];
    const float* W_conv = (const float*)d_in[2];
    const float* b_conv = (const float*)d_in[3];
    const float* W_x    = (const float*)d_in[4];
    const float* W_dt   = (const float*)d_in[5];
    const float* b_dt   = (const float*)d_in[6];
    const float* A_log  = (const float*)d_in[7];
    const float* Dp     = (const float*)d_in[8];
    const float* W_out  = (const float*)d_in[9];
    float* out = (float*)d_out;

    // 0) pre-round operands to tf32
    round_k<0><<<(ML * DM) / 1024, 256>>>(x);
    round_k<1><<<(DM * 2 * DI) / 1024, 256>>>(W_in);
    round_k<2><<<(DI * DI) / 1024, 256>>>(W_dt);
    round_k<3><<<(DI * DM) / 1024, 256>>>(W_out);

    // 1) xz = x @ W_in, split into x_inner / z
    gemm_tf32<1><<<dim3((2 * DI) / 128, ML / 128), 256>>>(nullptr, nullptr,
                                                          ML, 2 * DI, DM);
    // 2) depthwise causal conv + SiLU (writes exact + tf32 copies)
    conv_kernel<<<(ML * DI) / 256, 256>>>(W_conv, b_conv);
    // 3) BC = xc @ W_x
    bc_kernel<<<ML / 32, 256>>>(W_x);
    // 4) dt = softplus(xc @ W_dt + b_dt)
    gemm_tf32<2><<<dim3(DI / 128, ML / 128), 256>>>(nullptr, b_dt,
                                                    ML, DI, DI);
    // 5) chunked selective scan
    scanA_kernel<<<(GSEG * BB * DI) / 8, 128>>>(A_log);
    scanB_kernel<<<(BB * DI * DS) / 256, 256>>>();
    scanC_kernel<<<(GSEG * BB * DI) / 8, 128>>>(A_log, Dp);
    // 6) out = y @ W_out
    gemm_tf32<3><<<dim3(DM / 128, ML / 128), 256>>>(out, nullptr,
                                                    ML, DM, DI);
}

// round 5
// speedup vs baseline: 3.3851x; 1.0557x over previous
#include <cuda_runtime.h>
#include <cuda_bf16.h>

// Problem constants (fixed by the reference)
#define BB 2
#define LL 2048
#define DM 768
#define DI 1536
#define DS 16
#define DC 4
#define ML (BB*LL)          // 4096 rows
#define GSEG 16             // scan segments
#define LC (LL/GSEG)        // 128 steps per segment

// ---------------- scratch (device globals; no allocs allowed) ----------------
__device__ float g_xin[ML*DI];   // x_inner after W_in split
__device__ float g_z  [ML*DI];   // z gate
__device__ float g_xc [ML*DI];   // conv+silu output (exact)
__device__ float g_Bm [ML*DS];
__device__ float g_Cm [ML*DS];
__device__ float g_dt [ML*DI];
__device__ float g_y  [ML*DI];   // scan output, gated (tf32-rounded)
__device__ float g_h0 [GSEG*BB*DI*DS];
__device__ float g_P  [GSEG*BB*DI*DS];
__device__ float g_hin[GSEG*BB*DI*DS];
// tf32-prerounded operands
__device__ float g_xtf   [ML*DM];
__device__ float g_xctf  [ML*DI];
__device__ float g_wintf [DM*2*DI];
__device__ float g_wdttf [DI*DI];
__device__ float g_wouttf[DI*DM];

// ---------------- helpers -----------------------------------------------------
__device__ __forceinline__ unsigned f2tf32(float f) {
    unsigned u;
    asm("cvt.rna.tf32.f32 %0, %1;" : "=r"(u) : "f"(f));
    return u;
}
__device__ __forceinline__ float rtf(float f) { return __uint_as_float(f2tf32(f)); }

__device__ __forceinline__ void mma_tf32(float& c0, float& c1, float& c2, float& c3,
                                         unsigned a0, unsigned a1, unsigned a2, unsigned a3,
                                         unsigned b0, unsigned b1)
{
    asm volatile(
        "mma.sync.aligned.m16n8k8.row.col.f32.tf32.tf32.f32 "
        "{%0,%1,%2,%3}, {%4,%5,%6,%7}, {%8,%9}, {%0,%1,%2,%3};"
        : "+f"(c0), "+f"(c1), "+f"(c2), "+f"(c3)
        : "r"(a0), "r"(a1), "r"(a2), "r"(a3), "r"(b0), "r"(b1));
}

__device__ __forceinline__ void cp16(float* dst, const float* src) {
    unsigned saddr = (unsigned)__cvta_generic_to_shared(dst);
    asm volatile("cp.async.cg.shared.global [%0], [%1], 16;" :: "r"(saddr), "l"(src));
}

// ---------------- pre-round to tf32 -------------------------------------------
template <int ID>
__global__ void __launch_bounds__(256)
round_k(const float* __restrict__ src)
{
    float* dst = (ID == 0) ? g_xtf : (ID == 1) ? g_wintf
               : (ID == 2) ? g_wdttf : g_wouttf;
    const int i = (blockIdx.x * 256 + threadIdx.x) * 4;
    float4 v = *(const float4*)&src[i];
    v.x = rtf(v.x); v.y = rtf(v.y); v.z = rtf(v.z); v.w = rtf(v.w);
    *(float4*)&dst[i] = v;
}

// ---------------- TF32 tensor GEMM, 128x128 tile, 4-stage cp.async ------------
// MODE 1: A=g_xtf,  B=g_wintf,  out -> split g_xin / g_z   (N = 2*DI)
// MODE 2: A=g_xctf, B=g_wdttf,  out -> softplus(.+bias) -> g_dt
// MODE 3: A=g_y,    B=g_wouttf, out -> C0 param (d_out)
#define STAGES 4
#define AST 20     // A smem row stride (floats)
#define BST 136    // B smem row stride (floats)
#define ASZ (128*AST)   // 2560 floats / stage
#define BSZ (16*BST)    // 2176 floats / stage

template <int MODE>
__global__ void __launch_bounds__(256)
gemm_tf32(float* __restrict__ C0, const float* __restrict__ bias,
          int M, int N, int K)
{
    const float* __restrict__ A =
        (MODE == 1) ? (const float*)g_xtf : (MODE == 2) ? (const float*)g_xctf
                                                        : (const float*)g_y;
    const float* __restrict__ B =
        (MODE == 1) ? (const float*)g_wintf : (MODE == 2) ? (const float*)g_wdttf
                                                          : (const float*)g_wouttf;

    extern __shared__ float smem[];
    float* As = smem;                     // STAGES * ASZ
    float* Bs = smem + STAGES * ASZ;      // STAGES * BSZ

    const int tid  = threadIdx.x;
    const int lane = tid & 31;
    const int warp = tid >> 5;
    const int gid  = lane >> 2;    // 0..7
    const int tig  = lane & 3;     // 0..3
    const int wm   = (warp >> 2) * 64;   // 0 or 64
    const int wn   = (warp & 3) * 32;    // 0,32,64,96

    const int bm = blockIdx.y * 128;
    const int bn = blockIdx.x * 128;

    const int arow0 = tid >> 2;            // 0..63 (rows arow0, arow0+64)
    const int akq   = (tid & 3) * 4;       // 0,4,8,12
    const int bk0   = tid >> 5;            // 0..7 (k rows bk0, bk0+8)
    const int bc4   = (tid & 31) * 4;      // 0..124

    const float* aBase = A + (size_t)bm * K;
    const float* bBase = B + bn;

    const int nt = K / 16;

    // prologue: issue stages 0..2
#pragma unroll
    for (int t = 0; t < STAGES - 1; t++) {
        const int kt = t * 16;
        float* as = As + t * ASZ;
        float* bs = Bs + t * BSZ;
        cp16(&as[(arow0)      * AST + akq], &aBase[(size_t)(arow0)      * K + kt + akq]);
        cp16(&as[(arow0 + 64) * AST + akq], &aBase[(size_t)(arow0 + 64) * K + kt + akq]);
        cp16(&bs[(bk0)     * BST + bc4], &bBase[(size_t)(kt + bk0)     * N + bc4]);
        cp16(&bs[(bk0 + 8) * BST + bc4], &bBase[(size_t)(kt + bk0 + 8) * N + bc4]);
        asm volatile("cp.async.commit_group;");
    }

    float acc[4][4][4];
#pragma unroll
    for (int i = 0; i < 4; i++)
#pragma unroll
        for (int j = 0; j < 4; j++)
#pragma unroll
            for (int q = 0; q < 4; q++) acc[i][j][q] = 0.f;

    for (int i = 0; i < nt; i++) {
        asm volatile("cp.async.wait_group 2;");
        __syncthreads();

        // issue tile i+3 into stage (i+3)%4 (buffer computed at iter i-1)
        const int tn = i + STAGES - 1;
        if (tn < nt) {
            const int kt = tn * 16;
            const int s = tn & (STAGES - 1);
            float* as = As + s * ASZ;
            float* bs = Bs + s * BSZ;
            cp16(&as[(arow0)      * AST + akq], &aBase[(size_t)(arow0)      * K + kt + akq]);
            cp16(&as[(arow0 + 64) * AST + akq], &aBase[(size_t)(arow0 + 64) * K + kt + akq]);
            cp16(&bs[(bk0)     * BST + bc4], &bBase[(size_t)(kt + bk0)     * N + bc4]);
            cp16(&bs[(bk0 + 8) * BST + bc4], &bBase[(size_t)(kt + bk0 + 8) * N + bc4]);
        }
        asm volatile("cp.async.commit_group;");

        const float* as = As + (i & (STAGES - 1)) * ASZ;
        const float* bs = Bs + (i & (STAGES - 1)) * BSZ;
#pragma unroll
        for (int ks = 0; ks < 2; ks++) {
            const int k0 = ks * 8;
            unsigned af[4][4], bf[4][2];
#pragma unroll
            for (int mt = 0; mt < 4; mt++) {
                const int row = wm + mt * 16 + gid;
                af[mt][0] = __float_as_uint(as[(row)     * AST + k0 + tig]);
                af[mt][1] = __float_as_uint(as[(row + 8) * AST + k0 + tig]);
                af[mt][2] = __float_as_uint(as[(row)     * AST + k0 + tig + 4]);
                af[mt][3] = __float_as_uint(as[(row + 8) * AST + k0 + tig + 4]);
            }
#pragma unroll
            for (int nt2 = 0; nt2 < 4; nt2++) {
                const int col = wn + nt2 * 8 + gid;
                bf[nt2][0] = __float_as_uint(bs[(k0 + tig)     * BST + col]);
                bf[nt2][1] = __float_as_uint(bs[(k0 + tig + 4) * BST + col]);
            }
#pragma unroll
            for (int mt = 0; mt < 4; mt++)
#pragma unroll
                for (int nt2 = 0; nt2 < 4; nt2++)
                    mma_tf32(acc[mt][nt2][0], acc[mt][nt2][1],
                             acc[mt][nt2][2], acc[mt][nt2][3],
                             af[mt][0], af[mt][1], af[mt][2], af[mt][3],
                             bf[nt2][0], bf[nt2][1]);
        }
    }

    // ---- epilogue ----
#pragma unroll
    for (int mt = 0; mt < 4; mt++) {
#pragma unroll
        for (int nt2 = 0; nt2 < 4; nt2++) {
#pragma unroll
            for (int q = 0; q < 4; q++) {
                const int r = bm + wm + mt * 16 + gid + ((q >= 2) ? 8 : 0);
                const int c = bn + wn + nt2 * 8 + 2 * tig + (q & 1);
                float v = acc[mt][nt2][q];
                if (MODE == 1) {
                    if (c < DI) g_xin[(size_t)r * DI + c] = v;
                    else        g_z  [(size_t)r * DI + (c - DI)] = v;
                } else if (MODE == 2) {
                    v += bias[c];
                    v = fmaxf(v, 0.f) + log1pf(__expf(-fabsf(v)));
                    g_dt[(size_t)r * N + c] = v;
                } else {
                    C0[(size_t)r * N + c] = v;
                }
            }
        }
    }
}

// ---------------- depthwise causal conv (k=4) + bias + SiLU -------------------
__global__ void __launch_bounds__(256)
conv_kernel(const float* __restrict__ W_conv, const float* __restrict__ b_conv)
{
    const int idx = blockIdx.x * 256 + threadIdx.x;   // over ML*DI
    const int d = idx % DI;
    const int t = idx / DI;      // b*LL + l
    const int l = t % LL;

    float acc = b_conv[d];
#pragma unroll
    for (int j = 0; j < DC; j++) {
        const int ls = l + j - (DC - 1);
        if (ls >= 0)
            acc = fmaf(g_xin[(size_t)(t + j - (DC - 1)) * DI + d], W_conv[d * DC + j], acc);
    }
    const float sig = 1.f / (1.f + __expf(-acc));
    const float v = acc * sig;
    g_xc[idx]   = v;
    g_xctf[idx] = rtf(v);
}

// ---------------- BC = xc @ W_x  (N = 32) — 4 rows per warp -------------------
__global__ void __launch_bounds__(256)
bc_kernel(const float* __restrict__ W_x)
{
    const int warp = threadIdx.x >> 5;
    const int c = threadIdx.x & 31;
    const int row = (blockIdx.x * 8 + warp) * 4;
    const float* __restrict__ w = W_x + c;
    float a0 = 0.f, a1 = 0.f, a2 = 0.f, a3 = 0.f;
#pragma unroll 2
    for (int k = 0; k < DI; k += 4) {
        const float w0 = w[(k + 0) * 32];
        const float w1 = w[(k + 1) * 32];
        const float w2 = w[(k + 2) * 32];
        const float w3 = w[(k + 3) * 32];
        float4 x0 = *(const float4*)&g_xc[(size_t)(row + 0) * DI + k];
        float4 x1 = *(const float4*)&g_xc[(size_t)(row + 1) * DI + k];
        float4 x2 = *(const float4*)&g_xc[(size_t)(row + 2) * DI + k];
        float4 x3 = *(const float4*)&g_xc[(size_t)(row + 3) * DI + k];
        a0 = fmaf(x0.x, w0, fmaf(x0.y, w1, fmaf(x0.z, w2, fmaf(x0.w, w3, a0))));
        a1 = fmaf(x1.x, w0, fmaf(x1.y, w1, fmaf(x1.z, w2, fmaf(x1.w, w3, a1))));
        a2 = fmaf(x2.x, w0, fmaf(x2.y, w1, fmaf(x2.z, w2, fmaf(x2.w, w3, a2))));
        a3 = fmaf(x3.x, w0, fmaf(x3.y, w1, fmaf(x3.z, w2, fmaf(x3.w, w3, a3))));
    }
    float acc4[4] = {a0, a1, a2, a3};
#pragma unroll
    for (int r = 0; r < 4; r++) {
        if (c < DS) g_Bm[(size_t)(row + r) * DS + c]        = acc4[r];
        else        g_Cm[(size_t)(row + r) * DS + (c - DS)] = acc4[r];
    }
}

// ---------------- chunked selective scan --------------------------------------
__global__ void __launch_bounds__(128)
scanA_kernel(const float* __restrict__ A_log)
{
    const int grp = threadIdx.x >> 4;
    const int n   = threadIdx.x & 15;
    const int idx = blockIdx.x * 8 + grp;    // (g*BB+b)*DI + d
    const int d   = idx % DI;
    const int t   = idx / DI;
    const int b   = t % BB;
    const int g   = t / BB;

    const float a = -__expf(A_log[d * DS + n]);
    float h = 0.f, sdt = 0.f;
    const int base = b * LL + g * LC;

    float dtv = g_dt[(size_t)base * DI + d];
    float xcv = g_xc[(size_t)base * DI + d];
    float Bn  = g_Bm[(size_t)base * DS + n];

    for (int i = 0; i < LC; i++) {
        const float dt_c = dtv, xc_c = xcv, B_c = Bn;
        if (i + 1 < LC) {
            const int rb = base + i + 1;
            dtv = g_dt[(size_t)rb * DI + d];
            xcv = g_xc[(size_t)rb * DI + d];
            Bn  = g_Bm[(size_t)rb * DS + n];
        }
        h = fmaf(__expf(dt_c * a), h, dt_c * B_c * xc_c);
        sdt += dt_c;
    }
    g_h0[(size_t)idx * DS + n] = h;
    g_P [(size_t)idx * DS + n] = __expf(a * sdt);
}

__global__ void __launch_bounds__(256)
scanB_kernel()
{
    const int i = blockIdx.x * 256 + threadIdx.x;   // over BB*DI*DS
    const int n = i & 15;
    const int r = i >> 4;
    const int d = r % DI;
    const int b = r / DI;

    float h = 0.f;
#pragma unroll
    for (int g = 0; g < GSEG; g++) {
        const size_t j = (size_t)(((g * BB + b) * DI) + d) * DS + n;
        g_hin[j] = h;
        h = fmaf(g_P[j], h, g_h0[j]);
    }
}

__global__ void __launch_bounds__(128)
scanC_kernel(const float* __restrict__ A_log, const float* __restrict__ Dp)
{
    const int grp = threadIdx.x >> 4;
    const int n   = threadIdx.x & 15;
    const int idx = blockIdx.x * 8 + grp;
    const int d   = idx % DI;
    const int t   = idx / DI;
    const int b   = t % BB;
    const int g   = t / BB;

    const float a  = -__expf(A_log[d * DS + n]);
    const float Dv = Dp[d];
    float h = g_hin[(size_t)idx * DS + n];
    const int base = b * LL + g * LC;

    float dtv = g_dt[(size_t)base * DI + d];
    float xcv = g_xc[(size_t)base * DI + d];
    float Bn  = g_Bm[(size_t)base * DS + n];
    float Cn  = g_Cm[(size_t)base * DS + n];
    float zv  = g_z [(size_t)base * DI + d];

    for (int i = 0; i < LC; i++) {
        const float dt_c = dtv, xc_c = xcv, B_c = Bn, C_c = Cn, z_c = zv;
        if (i + 1 < LC) {
            const int rb = base + i + 1;
            dtv = g_dt[(size_t)rb * DI + d];
            xcv = g_xc[(size_t)rb * DI + d];
            Bn  = g_Bm[(size_t)rb * DS + n];
            Cn  = g_Cm[(size_t)rb * DS + n];
            zv  = g_z [(size_t)rb * DI + d];
        }

        h = fmaf(__expf(dt_c * a), h, dt_c * B_c * xc_c);

        float p = h * C_c;
        p += __shfl_xor_sync(0xffffffffu, p, 8);
        p += __shfl_xor_sync(0xffffffffu, p, 4);
        p += __shfl_xor_sync(0xffffffffu, p, 2);
        p += __shfl_xor_sync(0xffffffffu, p, 1);

        if (n == 0) {
            const float sig = 1.f / (1.f + __expf(-z_c));
            g_y[(size_t)(base + i) * DI + d] = rtf((p + xc_c * Dv) * (z_c * sig));
        }
    }
}

// ---------------- launch ------------------------------------------------------
extern "C" void kernel_launch(void* const* d_in, const int* in_sizes, int n_in,
                              void* d_out, int out_size)
{
    const float* x      = (const float*)d_in[0];
    const float* W_in   = (const float*)d_in[1];
    const float* W_conv = (const float*)d_in[2];
    const float* b_conv = (const float*)d_in[3];
    const float* W_x    = (const float*)d_in[4];
    const float* W_dt   = (const float*)d_in[5];
    const float* b_dt   = (const float*)d_in[6];
    const float* A_log  = (const float*)d_in[7];
    const float* Dp     = (const float*)d_in[8];
    const float* W_out  = (const float*)d_in[9];
    float* out = (float*)d_out;

    const int smem_bytes = (STAGES * ASZ + STAGES * BSZ) * 4;   // 75776 B
    cudaFuncSetAttribute(gemm_tf32<1>, cudaFuncAttributeMaxDynamicSharedMemorySize, smem_bytes);
    cudaFuncSetAttribute(gemm_tf32<2>, cudaFuncAttributeMaxDynamicSharedMemorySize, smem_bytes);
    cudaFuncSetAttribute(gemm_tf32<3>, cudaFuncAttributeMaxDynamicSharedMemorySize, smem_bytes);

    // 0) pre-round operands to tf32
    round_k<0><<<(ML * DM) / 1024, 256>>>(x);
    round_k<1><<<(DM * 2 * DI) / 1024, 256>>>(W_in);
    round_k<2><<<(DI * DI) / 1024, 256>>>(W_dt);
    round_k<3><<<(DI * DM) / 1024, 256>>>(W_out);

    // 1) xz = x @ W_in, split into x_inner / z
    gemm_tf32<1><<<dim3((2 * DI) / 128, ML / 128), 256, smem_bytes>>>(nullptr, nullptr,
                                                                     ML, 2 * DI, DM);
    // 2) depthwise causal conv + SiLU
    conv_kernel<<<(ML * DI) / 256, 256>>>(W_conv, b_conv);
    // 3) BC = xc @ W_x
    bc_kernel<<<ML / 32, 256>>>(W_x);
    // 4) dt = softplus(xc @ W_dt + b_dt)
    gemm_tf32<2><<<dim3(DI / 128, ML / 128), 256, smem_bytes>>>(nullptr, b_dt,
                                                                ML, DI, DI);
    // 5) chunked selective scan
    scanA_kernel<<<(GSEG * BB * DI) / 8, 128>>>(A_log);
    scanB_kernel<<<(BB * DI * DS) / 256, 256>>>();
    scanC_kernel<<<(GSEG * BB * DI) / 8, 128>>>(A_log, Dp);
    // 6) out = y @ W_out
    gemm_tf32<3><<<dim3(DM / 128, ML / 128), 256, smem_bytes>>>(out, nullptr,
                                                                ML, DM, DI);
}

// round 6
// speedup vs baseline: 3.4603x; 1.0222x over previous
#include <cuda_runtime.h>
#include <cuda_bf16.h>

// Problem constants (fixed by the reference)
#define BB 2
#define LL 2048
#define DM 768
#define DI 1536
#define DS 16
#define DC 4
#define ML (BB*LL)          // 4096 rows
#define GSEG 16             // scan segments
#define LC (LL/GSEG)        // 128 steps per segment

// ---------------- scratch (device globals; no allocs allowed) ----------------
__device__ float g_xin[ML*DI];   // x_inner after W_in split
__device__ float g_z  [ML*DI];   // z gate
__device__ float g_xc [ML*DI];   // conv+silu output (exact)
__device__ float g_Bm [ML*DS];
__device__ float g_Cm [ML*DS];
__device__ float g_dt [ML*DI];
__device__ float g_y  [ML*DI];   // scan output, gated (tf32-rounded)
__device__ float g_h0 [GSEG*BB*DI*DS];
__device__ float g_P  [GSEG*BB*DI*DS];
__device__ float g_hin[GSEG*BB*DI*DS];
// tf32-prerounded operands
__device__ float g_xtf   [ML*DM];
__device__ float g_xctf  [ML*DI];
__device__ float g_wintf [DM*2*DI];
__device__ float g_wdttf [DI*DI];
__device__ float g_wouttf[DI*DM];

// ---------------- helpers -----------------------------------------------------
__device__ __forceinline__ unsigned f2tf32(float f) {
    unsigned u;
    asm("cvt.rna.tf32.f32 %0, %1;" : "=r"(u) : "f"(f));
    return u;
}
__device__ __forceinline__ float rtf(float f) { return __uint_as_float(f2tf32(f)); }

__device__ __forceinline__ void mma_tf32(float& c0, float& c1, float& c2, float& c3,
                                         unsigned a0, unsigned a1, unsigned a2, unsigned a3,
                                         unsigned b0, unsigned b1)
{
    asm volatile(
        "mma.sync.aligned.m16n8k8.row.col.f32.tf32.tf32.f32 "
        "{%0,%1,%2,%3}, {%4,%5,%6,%7}, {%8,%9}, {%0,%1,%2,%3};"
        : "+f"(c0), "+f"(c1), "+f"(c2), "+f"(c3)
        : "r"(a0), "r"(a1), "r"(a2), "r"(a3), "r"(b0), "r"(b1));
}

__device__ __forceinline__ void cp16(float* dst, const float* src) {
    unsigned saddr = (unsigned)__cvta_generic_to_shared(dst);
    asm volatile("cp.async.cg.shared.global [%0], [%1], 16;" :: "r"(saddr), "l"(src));
}

// ---------------- pre-round to tf32 -------------------------------------------
template <int ID>
__global__ void __launch_bounds__(256)
round_k(const float* __restrict__ src)
{
    float* dst = (ID == 0) ? g_xtf : (ID == 1) ? g_wintf
               : (ID == 2) ? g_wdttf : g_wouttf;
    const int i = (blockIdx.x * 256 + threadIdx.x) * 4;
    float4 v = *(const float4*)&src[i];
    v.x = rtf(v.x); v.y = rtf(v.y); v.z = rtf(v.z); v.w = rtf(v.w);
    *(float4*)&dst[i] = v;
}

// ---------------- TF32 tensor GEMM, 128x128 tile, 3-stage cp.async ------------
// MODE 1: A=g_xtf,  B=g_wintf,  out -> split g_xin / g_z   (N = 2*DI)
// MODE 2: A=g_xctf, B=g_wdttf,  out -> softplus(.+bias) -> g_dt
// MODE 3: A=g_y,    B=g_wouttf, out -> C0 param (d_out)
#define STAGES 3
#define AST 20     // A smem row stride (floats)
#define BST 136    // B smem row stride (floats)
#define ASZ (128*AST)   // 2560 floats / stage
#define BSZ (16*BST)    // 2176 floats / stage

template <int MODE>
__global__ void __launch_bounds__(256, 2)
gemm_tf32(float* __restrict__ C0, const float* __restrict__ bias,
          int M, int N, int K)
{
    const float* __restrict__ A =
        (MODE == 1) ? (const float*)g_xtf : (MODE == 2) ? (const float*)g_xctf
                                                        : (const float*)g_y;
    const float* __restrict__ B =
        (MODE == 1) ? (const float*)g_wintf : (MODE == 2) ? (const float*)g_wdttf
                                                          : (const float*)g_wouttf;

    extern __shared__ float smem[];
    float* As = smem;                     // STAGES * ASZ
    float* Bs = smem + STAGES * ASZ;      // STAGES * BSZ

    const int tid  = threadIdx.x;
    const int lane = tid & 31;
    const int warp = tid >> 5;
    const int gid  = lane >> 2;    // 0..7
    const int tig  = lane & 3;     // 0..3
    const int wm   = (warp >> 2) * 64;   // 0 or 64
    const int wn   = (warp & 3) * 32;    // 0,32,64,96

    const int bm = blockIdx.y * 128;
    const int bn = blockIdx.x * 128;

    const int arow0 = tid >> 2;            // 0..63 (rows arow0, arow0+64)
    const int akq   = (tid & 3) * 4;       // 0,4,8,12
    const int bk0   = tid >> 5;            // 0..7 (k rows bk0, bk0+8)
    const int bc4   = (tid & 31) * 4;      // 0..124

    const float* aBase = A + (size_t)bm * K;
    const float* bBase = B + bn;

    const int nt = K / 16;

    // prologue: issue stages 0..STAGES-2
#pragma unroll
    for (int t = 0; t < STAGES - 1; t++) {
        const int kt = t * 16;
        float* as = As + t * ASZ;
        float* bs = Bs + t * BSZ;
        cp16(&as[(arow0)      * AST + akq], &aBase[(size_t)(arow0)      * K + kt + akq]);
        cp16(&as[(arow0 + 64) * AST + akq], &aBase[(size_t)(arow0 + 64) * K + kt + akq]);
        cp16(&bs[(bk0)     * BST + bc4], &bBase[(size_t)(kt + bk0)     * N + bc4]);
        cp16(&bs[(bk0 + 8) * BST + bc4], &bBase[(size_t)(kt + bk0 + 8) * N + bc4]);
        asm volatile("cp.async.commit_group;");
    }

    float acc[4][4][4];
#pragma unroll
    for (int i = 0; i < 4; i++)
#pragma unroll
        for (int j = 0; j < 4; j++)
#pragma unroll
            for (int q = 0; q < 4; q++) acc[i][j][q] = 0.f;

    int stage = 0, nstage = STAGES - 1;
    for (int i = 0; i < nt; i++) {
        asm volatile("cp.async.wait_group %0;" :: "n"(STAGES - 2));
        __syncthreads();

        // issue tile i+STAGES-1 into its stage
        const int tn = i + STAGES - 1;
        if (tn < nt) {
            const int kt = tn * 16;
            float* as = As + nstage * ASZ;
            float* bs = Bs + nstage * BSZ;
            cp16(&as[(arow0)      * AST + akq], &aBase[(size_t)(arow0)      * K + kt + akq]);
            cp16(&as[(arow0 + 64) * AST + akq], &aBase[(size_t)(arow0 + 64) * K + kt + akq]);
            cp16(&bs[(bk0)     * BST + bc4], &bBase[(size_t)(kt + bk0)     * N + bc4]);
            cp16(&bs[(bk0 + 8) * BST + bc4], &bBase[(size_t)(kt + bk0 + 8) * N + bc4]);
        }
        asm volatile("cp.async.commit_group;");
        nstage = (nstage + 1 == STAGES) ? 0 : nstage + 1;

        const float* as = As + stage * ASZ;
        const float* bs = Bs + stage * BSZ;
        stage = (stage + 1 == STAGES) ? 0 : stage + 1;
#pragma unroll
        for (int ks = 0; ks < 2; ks++) {
            const int k0 = ks * 8;
            unsigned af[4][4], bf[4][2];
#pragma unroll
            for (int mt = 0; mt < 4; mt++) {
                const int row = wm + mt * 16 + gid;
                af[mt][0] = __float_as_uint(as[(row)     * AST + k0 + tig]);
                af[mt][1] = __float_as_uint(as[(row + 8) * AST + k0 + tig]);
                af[mt][2] = __float_as_uint(as[(row)     * AST + k0 + tig + 4]);
                af[mt][3] = __float_as_uint(as[(row + 8) * AST + k0 + tig + 4]);
            }
#pragma unroll
            for (int nt2 = 0; nt2 < 4; nt2++) {
                const int col = wn + nt2 * 8 + gid;
                bf[nt2][0] = __float_as_uint(bs[(k0 + tig)     * BST + col]);
                bf[nt2][1] = __float_as_uint(bs[(k0 + tig + 4) * BST + col]);
            }
#pragma unroll
            for (int mt = 0; mt < 4; mt++)
#pragma unroll
                for (int nt2 = 0; nt2 < 4; nt2++)
                    mma_tf32(acc[mt][nt2][0], acc[mt][nt2][1],
                             acc[mt][nt2][2], acc[mt][nt2][3],
                             af[mt][0], af[mt][1], af[mt][2], af[mt][3],
                             bf[nt2][0], bf[nt2][1]);
        }
    }

    // ---- epilogue ----
#pragma unroll
    for (int mt = 0; mt < 4; mt++) {
#pragma unroll
        for (int nt2 = 0; nt2 < 4; nt2++) {
#pragma unroll
            for (int q = 0; q < 4; q++) {
                const int r = bm + wm + mt * 16 + gid + ((q >= 2) ? 8 : 0);
                const int c = bn + wn + nt2 * 8 + 2 * tig + (q & 1);
                float v = acc[mt][nt2][q];
                if (MODE == 1) {
                    if (c < DI) g_xin[(size_t)r * DI + c] = v;
                    else        g_z  [(size_t)r * DI + (c - DI)] = v;
                } else if (MODE == 2) {
                    v += bias[c];
                    v = fmaxf(v, 0.f) + log1pf(__expf(-fabsf(v)));
                    g_dt[(size_t)r * N + c] = v;
                } else {
                    C0[(size_t)r * N + c] = v;
                }
            }
        }
    }
}

// ---------------- depthwise causal conv (k=4) + bias + SiLU -------------------
__global__ void __launch_bounds__(256)
conv_kernel(const float* __restrict__ W_conv, const float* __restrict__ b_conv)
{
    const int idx = blockIdx.x * 256 + threadIdx.x;   // over ML*DI
    const int d = idx % DI;
    const int t = idx / DI;      // b*LL + l
    const int l = t % LL;

    float acc = b_conv[d];
#pragma unroll
    for (int j = 0; j < DC; j++) {
        const int ls = l + j - (DC - 1);
        if (ls >= 0)
            acc = fmaf(g_xin[(size_t)(t + j - (DC - 1)) * DI + d], W_conv[d * DC + j], acc);
    }
    const float sig = 1.f / (1.f + __expf(-acc));
    const float v = acc * sig;
    g_xc[idx]   = v;
    g_xctf[idx] = rtf(v);
}

// ---------------- BC = xc @ W_x  (N = 32) — 4 rows per warp -------------------
__global__ void __launch_bounds__(256)
bc_kernel(const float* __restrict__ W_x)
{
    const int warp = threadIdx.x >> 5;
    const int c = threadIdx.x & 31;
    const int row = (blockIdx.x * 8 + warp) * 4;
    const float* __restrict__ w = W_x + c;
    float a0 = 0.f, a1 = 0.f, a2 = 0.f, a3 = 0.f;
#pragma unroll 2
    for (int k = 0; k < DI; k += 4) {
        const float w0 = w[(k + 0) * 32];
        const float w1 = w[(k + 1) * 32];
        const float w2 = w[(k + 2) * 32];
        const float w3 = w[(k + 3) * 32];
        float4 x0 = *(const float4*)&g_xc[(size_t)(row + 0) * DI + k];
        float4 x1 = *(const float4*)&g_xc[(size_t)(row + 1) * DI + k];
        float4 x2 = *(const float4*)&g_xc[(size_t)(row + 2) * DI + k];
        float4 x3 = *(const float4*)&g_xc[(size_t)(row + 3) * DI + k];
        a0 = fmaf(x0.x, w0, fmaf(x0.y, w1, fmaf(x0.z, w2, fmaf(x0.w, w3, a0))));
        a1 = fmaf(x1.x, w0, fmaf(x1.y, w1, fmaf(x1.z, w2, fmaf(x1.w, w3, a1))));
        a2 = fmaf(x2.x, w0, fmaf(x2.y, w1, fmaf(x2.z, w2, fmaf(x2.w, w3, a2))));
        a3 = fmaf(x3.x, w0, fmaf(x3.y, w1, fmaf(x3.z, w2, fmaf(x3.w, w3, a3))));
    }
    float acc4[4] = {a0, a1, a2, a3};
#pragma unroll
    for (int r = 0; r < 4; r++) {
        if (c < DS) g_Bm[(size_t)(row + r) * DS + c]        = acc4[r];
        else        g_Cm[(size_t)(row + r) * DS + (c - DS)] = acc4[r];
    }
}

// ---------------- chunked selective scan --------------------------------------
__global__ void __launch_bounds__(128)
scanA_kernel(const float* __restrict__ A_log)
{
    const int grp = threadIdx.x >> 4;
    const int n   = threadIdx.x & 15;
    const int idx = blockIdx.x * 8 + grp;    // (g*BB+b)*DI + d
    const int d   = idx % DI;
    const int t   = idx / DI;
    const int b   = t % BB;
    const int g   = t / BB;

    const float a = -__expf(A_log[d * DS + n]);
    float h = 0.f, sdt = 0.f;
    const int base = b * LL + g * LC;

    float dtv = g_dt[(size_t)base * DI + d];
    float xcv = g_xc[(size_t)base * DI + d];
    float Bn  = g_Bm[(size_t)base * DS + n];

    for (int i = 0; i < LC; i++) {
        const float dt_c = dtv, xc_c = xcv, B_c = Bn;
        if (i + 1 < LC) {
            const int rb = base + i + 1;
            dtv = g_dt[(size_t)rb * DI + d];
            xcv = g_xc[(size_t)rb * DI + d];
            Bn  = g_Bm[(size_t)rb * DS + n];
        }
        h = fmaf(__expf(dt_c * a), h, dt_c * B_c * xc_c);
        sdt += dt_c;
    }
    g_h0[(size_t)idx * DS + n] = h;
    g_P [(size_t)idx * DS + n] = __expf(a * sdt);
}

__global__ void __launch_bounds__(256)
scanB_kernel()
{
    const int i = blockIdx.x * 256 + threadIdx.x;   // over BB*DI*DS
    const int n = i & 15;
    const int r = i >> 4;
    const int d = r % DI;
    const int b = r / DI;

    float h = 0.f;
#pragma unroll
    for (int g = 0; g < GSEG; g++) {
        const size_t j = (size_t)(((g * BB + b) * DI) + d) * DS + n;
        g_hin[j] = h;
        h = fmaf(g_P[j], h, g_h0[j]);
    }
}

__global__ void __launch_bounds__(128)
scanC_kernel(const float* __restrict__ A_log, const float* __restrict__ Dp)
{
    const int grp = threadIdx.x >> 4;
    const int n   = threadIdx.x & 15;
    const int idx = blockIdx.x * 8 + grp;
    const int d   = idx % DI;
    const int t   = idx / DI;
    const int b   = t % BB;
    const int g   = t / BB;

    const float a  = -__expf(A_log[d * DS + n]);
    const float Dv = Dp[d];
    float h = g_hin[(size_t)idx * DS + n];
    const int base = b * LL + g * LC;

    float dtv = g_dt[(size_t)base * DI + d];
    float xcv = g_xc[(size_t)base * DI + d];
    float Bn  = g_Bm[(size_t)base * DS + n];
    float Cn  = g_Cm[(size_t)base * DS + n];
    float zv  = g_z [(size_t)base * DI + d];

    for (int i = 0; i < LC; i++) {
        const float dt_c = dtv, xc_c = xcv, B_c = Bn, C_c = Cn, z_c = zv;
        if (i + 1 < LC) {
            const int rb = base + i + 1;
            dtv = g_dt[(size_t)rb * DI + d];
            xcv = g_xc[(size_t)rb * DI + d];
            Bn  = g_Bm[(size_t)rb * DS + n];
            Cn  = g_Cm[(size_t)rb * DS + n];
            zv  = g_z [(size_t)rb * DI + d];
        }

        h = fmaf(__expf(dt_c * a), h, dt_c * B_c * xc_c);

        float p = h * C_c;
        p += __shfl_xor_sync(0xffffffffu, p, 8);
        p += __shfl_xor_sync(0xffffffffu, p, 4);
        p += __shfl_xor_sync(0xffffffffu, p, 2);
        p += __shfl_xor_sync(0xffffffffu, p, 1);

        if (n == 0) {
            const float sig = 1.f / (1.f + __expf(-z_c));
            g_y[(size_t)(base + i) * DI + d] = rtf((p + xc_c * Dv) * (z_c * sig));
        }
    }
}

// ---------------- launch ------------------------------------------------------
extern "C" void kernel_launch(void* const* d_in, const int* in_sizes, int n_in,
                              void* d_out, int out_size)
{
    const float* x      = (const float*)d_in[0];
    const float* W_in   = (const float*)d_in[1];
    const float* W_conv = (const float*)d_in[2];
    const float* b_conv = (const float*)d_in[3];
    const float* W_x    = (const float*)d_in[4];
    const float* W_dt   = (const float*)d_in[5];
    const float* b_dt   = (const float*)d_in[6];
    const float* A_log  = (const float*)d_in[7];
    const float* Dp     = (const float*)d_in[8];
    const float* W_out  = (const float*)d_in[9];
    float* out = (float*)d_out;

    const int smem_bytes = (STAGES * ASZ + STAGES * BSZ) * 4;   // 56832 B
    cudaFuncSetAttribute(gemm_tf32<1>, cudaFuncAttributeMaxDynamicSharedMemorySize, smem_bytes);
    cudaFuncSetAttribute(gemm_tf32<2>, cudaFuncAttributeMaxDynamicSharedMemorySize, smem_bytes);
    cudaFuncSetAttribute(gemm_tf32<3>, cudaFuncAttributeMaxDynamicSharedMemorySize, smem_bytes);

    // 0) pre-round operands to tf32
    round_k<0><<<(ML * DM) / 1024, 256>>>(x);
    round_k<1><<<(DM * 2 * DI) / 1024, 256>>>(W_in);
    round_k<2><<<(DI * DI) / 1024, 256>>>(W_dt);
    round_k<3><<<(DI * DM) / 1024, 256>>>(W_out);

    // 1) xz = x @ W_in, split into x_inner / z
    gemm_tf32<1><<<dim3((2 * DI) / 128, ML / 128), 256, smem_bytes>>>(nullptr, nullptr,
                                                                     ML, 2 * DI, DM);
    // 2) depthwise causal conv + SiLU
    conv_kernel<<<(ML * DI) / 256, 256>>>(W_conv, b_conv);
    // 3) BC = xc @ W_x
    bc_kernel<<<ML / 32, 256>>>(W_x);
    // 4) dt = softplus(xc @ W_dt + b_dt)
    gemm_tf32<2><<<dim3(DI / 128, ML / 128), 256, smem_bytes>>>(nullptr, b_dt,
                                                                ML, DI, DI);
    // 5) chunked selective scan
    scanA_kernel<<<(GSEG * BB * DI) / 8, 128>>>(A_log);
    scanB_kernel<<<(BB * DI * DS) / 256, 256>>>();
    scanC_kernel<<<(GSEG * BB * DI) / 8, 128>>>(A_log, Dp);
    // 6) out = y @ W_out
    gemm_tf32<3><<<dim3(DM / 128, ML / 128), 256, smem_bytes>>>(out, nullptr,
                                                                ML, DM, DI);
}

// round 8
// speedup vs baseline: 4.4656x; 1.2905x over previous
#include <cuda_runtime.h>
#include <cuda_fp16.h>

// Problem constants (fixed by the reference)
#define BB 2
#define LL 2048
#define DM 768
#define DI 1536
#define DS 16
#define DC 4
#define ML (BB*LL)          // 4096 rows
#define GSEG 16             // scan segments
#define LC (LL/GSEG)        // 128 steps per segment

// ---------------- scratch (device globals; no allocs allowed) ----------------
__device__ float g_xin[ML*DI];
__device__ float g_z  [ML*DI];
__device__ float g_xc [ML*DI];
__device__ float g_Bm [ML*DS];
__device__ float g_Cm [ML*DS];
__device__ float g_dt [ML*DI];
__device__ float g_h0 [GSEG*BB*DI*DS];
__device__ float g_P  [GSEG*BB*DI*DS];
__device__ float g_hin[GSEG*BB*DI*DS];
// fp16 operands (original layouts)
__device__ __align__(16) __half g_x16  [ML*DM];
__device__ __align__(16) __half g_xc16 [ML*DI];
__device__ __align__(16) __half g_y16  [ML*DI];
__device__ __align__(16) __half g_win16[DM*2*DI];
__device__ __align__(16) __half g_wdt16[DI*DI];
__device__ __align__(16) __half g_wout16[DI*DM];

// ---------------- helpers -----------------------------------------------------
__device__ __forceinline__ unsigned s2u(const void* p) {
    return (unsigned)__cvta_generic_to_shared(p);
}
__device__ __forceinline__ void cp16(unsigned sdst, const void* src) {
    asm volatile("cp.async.cg.shared.global [%0], [%1], 16;" :: "r"(sdst), "l"(src));
}

#define LDSM_X4(r0,r1,r2,r3,addr) \
    asm volatile("ldmatrix.sync.aligned.m8n8.x4.shared.b16 {%0,%1,%2,%3}, [%4];" \
        : "=r"(r0), "=r"(r1), "=r"(r2), "=r"(r3) : "r"(addr))
#define LDSM_X4T(r0,r1,r2,r3,addr) \
    asm volatile("ldmatrix.sync.aligned.m8n8.x4.trans.shared.b16 {%0,%1,%2,%3}, [%4];" \
        : "=r"(r0), "=r"(r1), "=r"(r2), "=r"(r3) : "r"(addr))

__device__ __forceinline__ void mma16816(float* c, const unsigned* a, const unsigned* b)
{
    asm volatile(
        "mma.sync.aligned.m16n8k16.row.col.f32.f16.f16.f32 "
        "{%0,%1,%2,%3}, {%4,%5,%6,%7}, {%8,%9}, {%0,%1,%2,%3};"
        : "+f"(c[0]), "+f"(c[1]), "+f"(c[2]), "+f"(c[3])
        : "r"(a[0]), "r"(a[1]), "r"(a[2]), "r"(a[3]), "r"(b[0]), "r"(b[1]));
}

// ---------------- fp32 -> fp16 casts ------------------------------------------
// ID: 0 -> g_x16, 1 -> g_win16, 2 -> g_wdt16, 3 -> g_wout16
template <int ID>
__global__ void __launch_bounds__(256)
cvt16(const float* __restrict__ src)
{
    __half* dst = (ID == 0) ? g_x16 : (ID == 1) ? g_win16
                : (ID == 2) ? g_wdt16 : g_wout16;
    const int i = (blockIdx.x * 256 + threadIdx.x) * 4;
    float4 v = *(const float4*)&src[i];
    __half2* d2 = (__half2*)&dst[i];
    d2[0] = __floats2half2_rn(v.x, v.y);
    d2[1] = __floats2half2_rn(v.z, v.w);
}

// ---------------- fp16 tensor GEMM: 128x128 tile, BK=64, 3-stage cp.async -----
// A [M][K] row-major fp16, B [K][N] row-major fp16 (original layout).
// A smem: 128 rows x 128B, chunk swizzle c^=(r&7).
// B smem: 64 k-rows x 256B (128 n-cols), chunk swizzle c^=(r&7) (low 3 bits).
// MODE 1: A=g_x16,  B=g_win16,  out -> split g_xin / g_z  (N=3072, K=768)
// MODE 2: A=g_xc16, B=g_wdt16,  out -> softplus -> g_dt   (N=1536, K=1536)
// MODE 3: A=g_y16,  B=g_wout16, out -> d_out              (N=768,  K=1536)
#define STAGES 3
#define ATB 16384
#define BTB 16384

template <int MODE>
__global__ void __launch_bounds__(256, 2)
gemm_f16(float* __restrict__ C0, const float* __restrict__ bias, int N, int K)
{
    const __half* __restrict__ A =
        (MODE == 1) ? g_x16 : (MODE == 2) ? g_xc16 : g_y16;
    const __half* __restrict__ B =
        (MODE == 1) ? g_win16 : (MODE == 2) ? g_wdt16 : g_wout16;

    extern __shared__ char sm[];
    char* Asm = sm;                     // STAGES * ATB
    char* Bsm = sm + STAGES * ATB;      // STAGES * BTB

    const int tid  = threadIdx.x;
    const int lane = tid & 31;
    const int warp = tid >> 5;
    const int gid  = lane >> 2;
    const int tig  = lane & 3;
    const int wm   = (warp >> 2) * 64;
    const int wn   = (warp & 3) * 32;

    const int bm = blockIdx.y * 128;
    const int bn = blockIdx.x * 128;
    const int nt = K / 64;

    auto load_tile = [&](int kt, int s) {
        char* as = Asm + s * ATB;
        char* bs = Bsm + s * BTB;
#pragma unroll
        for (int it = 0; it < 4; it++) {
            const int q = tid + it * 256;       // 1024 chunks: 128 rows x 8
            const int r = q >> 3, c = q & 7;
            cp16(s2u(as) + r * 128 + ((c ^ (r & 7)) << 4),
                 A + (size_t)(bm + r) * K + kt + c * 8);
        }
#pragma unroll
        for (int it = 0; it < 4; it++) {
            const int q = tid + it * 256;       // 1024 chunks: 64 rows x 16
            const int r = q >> 4, c = q & 15;
            cp16(s2u(bs) + r * 256 + ((c ^ (r & 7)) << 4),
                 B + (size_t)(kt + r) * N + bn + c * 8);
        }
    };

    load_tile(0, 0);
    asm volatile("cp.async.commit_group;");
    load_tile(64, 1);
    asm volatile("cp.async.commit_group;");

    float acc[4][4][4];
#pragma unroll
    for (int i = 0; i < 4; i++)
#pragma unroll
        for (int j = 0; j < 4; j++)
#pragma unroll
            for (int q = 0; q < 4; q++) acc[i][j][q] = 0.f;

    for (int i = 0; i < nt; i++) {
        asm volatile("cp.async.wait_group 1;");
        __syncthreads();

        if (i + 2 < nt) load_tile((i + 2) * 64, (i + 2) % STAGES);
        asm volatile("cp.async.commit_group;");

        const unsigned asb = s2u(Asm + (i % STAGES) * ATB);
        const unsigned bsb = s2u(Bsm + (i % STAGES) * BTB);

#pragma unroll
        for (int ks = 0; ks < 4; ks++) {
            unsigned af[4][4];
#pragma unroll
            for (int mt = 0; mt < 4; mt++) {
                const int row = wm + mt * 16 + (lane & 15);
                const unsigned ad = asb + row * 128
                                  + (((2 * ks + (lane >> 4)) ^ (row & 7)) << 4);
                LDSM_X4(af[mt][0], af[mt][1], af[mt][2], af[mt][3], ad);
            }
            unsigned bf[4][2];
#pragma unroll
            for (int p = 0; p < 2; p++) {
                const int krow = ks * 16 + (lane & 15);
                const int nch = (wn >> 3) + p * 2 + (lane >> 4);
                const unsigned bd = bsb + krow * 256 + ((nch ^ (krow & 7)) << 4);
                LDSM_X4T(bf[2 * p][0], bf[2 * p][1], bf[2 * p + 1][0], bf[2 * p + 1][1], bd);
            }
#pragma unroll
            for (int mt = 0; mt < 4; mt++)
#pragma unroll
                for (int nn = 0; nn < 4; nn++)
                    mma16816(acc[mt][nn], af[mt], bf[nn]);
        }
    }

    // ---- epilogue ----
#pragma unroll
    for (int mt = 0; mt < 4; mt++) {
#pragma unroll
        for (int nn = 0; nn < 4; nn++) {
#pragma unroll
            for (int q = 0; q < 4; q++) {
                const int r = bm + wm + mt * 16 + gid + ((q >= 2) ? 8 : 0);
                const int c = bn + wn + nn * 8 + 2 * tig + (q & 1);
                float v = acc[mt][nn][q];
                if (MODE == 1) {
                    if (c < DI) g_xin[(size_t)r * DI + c] = v;
                    else        g_z  [(size_t)r * DI + (c - DI)] = v;
                } else if (MODE == 2) {
                    v += bias[c];
                    v = fmaxf(v, 0.f) + log1pf(__expf(-fabsf(v)));
                    g_dt[(size_t)r * DI + c] = v;
                } else {
                    C0[(size_t)r * DM + c] = v;
                }
            }
        }
    }
}

// ---------------- depthwise causal conv (k=4) + bias + SiLU -------------------
__global__ void __launch_bounds__(256)
conv_kernel(const float* __restrict__ W_conv, const float* __restrict__ b_conv)
{
    const int idx = blockIdx.x * 256 + threadIdx.x;   // over ML*DI
    const int d = idx % DI;
    const int t = idx / DI;
    const int l = t % LL;

    float acc = b_conv[d];
#pragma unroll
    for (int j = 0; j < DC; j++) {
        const int ls = l + j - (DC - 1);
        if (ls >= 0)
            acc = fmaf(g_xin[(size_t)(t + j - (DC - 1)) * DI + d], W_conv[d * DC + j], acc);
    }
    const float sig = 1.f / (1.f + __expf(-acc));
    const float v = acc * sig;
    g_xc[idx]   = v;
    g_xc16[idx] = __float2half(v);
}

// ---------------- BC = xc @ W_x  (N = 32) — 4 rows per warp -------------------
__global__ void __launch_bounds__(256)
bc_kernel(const float* __restrict__ W_x)
{
    const int warp = threadIdx.x >> 5;
    const int c = threadIdx.x & 31;
    const int row = (blockIdx.x * 8 + warp) * 4;
    const float* __restrict__ w = W_x + c;
    float a0 = 0.f, a1 = 0.f, a2 = 0.f, a3 = 0.f;
#pragma unroll 2
    for (int k = 0; k < DI; k += 4) {
        const float w0 = w[(k + 0) * 32];
        const float w1 = w[(k + 1) * 32];
        const float w2 = w[(k + 2) * 32];
        const float w3 = w[(k + 3) * 32];
        float4 x0 = *(const float4*)&g_xc[(size_t)(row + 0) * DI + k];
        float4 x1 = *(const float4*)&g_xc[(size_t)(row + 1) * DI + k];
        float4 x2 = *(const float4*)&g_xc[(size_t)(row + 2) * DI + k];
        float4 x3 = *(const float4*)&g_xc[(size_t)(row + 3) * DI + k];
        a0 = fmaf(x0.x, w0, fmaf(x0.y, w1, fmaf(x0.z, w2, fmaf(x0.w, w3, a0))));
        a1 = fmaf(x1.x, w0, fmaf(x1.y, w1, fmaf(x1.z, w2, fmaf(x1.w, w3, a1))));
        a2 = fmaf(x2.x, w0, fmaf(x2.y, w1, fmaf(x2.z, w2, fmaf(x2.w, w3, a2))));
        a3 = fmaf(x3.x, w0, fmaf(x3.y, w1, fmaf(x3.z, w2, fmaf(x3.w, w3, a3))));
    }
    float acc4[4] = {a0, a1, a2, a3};
#pragma unroll
    for (int r = 0; r < 4; r++) {
        if (c < DS) g_Bm[(size_t)(row + r) * DS + c]        = acc4[r];
        else        g_Cm[(size_t)(row + r) * DS + (c - DS)] = acc4[r];
    }
}

// ---------------- chunked selective scan --------------------------------------
__global__ void __launch_bounds__(128)
scanA_kernel(const float* __restrict__ A_log)
{
    const int grp = threadIdx.x >> 4;
    const int n   = threadIdx.x & 15;
    const int idx = blockIdx.x * 8 + grp;    // (g*BB+b)*DI + d
    const int d   = idx % DI;
    const int t   = idx / DI;
    const int b   = t % BB;
    const int g   = t / BB;

    const float a = -__expf(A_log[d * DS + n]);
    float h = 0.f, sdt = 0.f;
    const int base = b * LL + g * LC;

    float dtv = g_dt[(size_t)base * DI + d];
    float xcv = g_xc[(size_t)base * DI + d];
    float Bn  = g_Bm[(size_t)base * DS + n];

    for (int i = 0; i < LC; i++) {
        const float dt_c = dtv, xc_c = xcv, B_c = Bn;
        if (i + 1 < LC) {
            const int rb = base + i + 1;
            dtv = g_dt[(size_t)rb * DI + d];
            xcv = g_xc[(size_t)rb * DI + d];
            Bn  = g_Bm[(size_t)rb * DS + n];
        }
        h = fmaf(__expf(dt_c * a), h, dt_c * B_c * xc_c);
        sdt += dt_c;
    }
    g_h0[(size_t)idx * DS + n] = h;
    g_P [(size_t)idx * DS + n] = __expf(a * sdt);
}

__global__ void __launch_bounds__(256)
scanB_kernel()
{
    const int i = blockIdx.x * 256 + threadIdx.x;   // over BB*DI*DS
    const int n = i & 15;
    const int r = i >> 4;
    const int d = r % DI;
    const int b = r / DI;

    float h = 0.f;
#pragma unroll
    for (int g = 0; g < GSEG; g++) {
        const size_t j = (size_t)(((g * BB + b) * DI) + d) * DS + n;
        g_hin[j] = h;
        h = fmaf(g_P[j], h, g_h0[j]);
    }
}

__global__ void __launch_bounds__(128)
scanC_kernel(const float* __restrict__ A_log, const float* __restrict__ Dp)
{
    const int grp = threadIdx.x >> 4;
    const int n   = threadIdx.x & 15;
    const int idx = blockIdx.x * 8 + grp;
    const int d   = idx % DI;
    const int t   = idx / DI;
    const int b   = t % BB;
    const int g   = t / BB;

    const float a  = -__expf(A_log[d * DS + n]);
    const float Dv = Dp[d];
    float h = g_hin[(size_t)idx * DS + n];
    const int base = b * LL + g * LC;

    float dtv = g_dt[(size_t)base * DI + d];
    float xcv = g_xc[(size_t)base * DI + d];
    float Bn  = g_Bm[(size_t)base * DS + n];
    float Cn  = g_Cm[(size_t)base * DS + n];
    float zv  = g_z [(size_t)base * DI + d];

    for (int i = 0; i < LC; i++) {
        const float dt_c = dtv, xc_c = xcv, B_c = Bn, C_c = Cn, z_c = zv;
        if (i + 1 < LC) {
            const int rb = base + i + 1;
            dtv = g_dt[(size_t)rb * DI + d];
            xcv = g_xc[(size_t)rb * DI + d];
            Bn  = g_Bm[(size_t)rb * DS + n];
            Cn  = g_Cm[(size_t)rb * DS + n];
            zv  = g_z [(size_t)rb * DI + d];
        }

        h = fmaf(__expf(dt_c * a), h, dt_c * B_c * xc_c);

        float p = h * C_c;
        p += __shfl_xor_sync(0xffffffffu, p, 8);
        p += __shfl_xor_sync(0xffffffffu, p, 4);
        p += __shfl_xor_sync(0xffffffffu, p, 2);
        p += __shfl_xor_sync(0xffffffffu, p, 1);

        if (n == 0) {
            const float sig = 1.f / (1.f + __expf(-z_c));
            const float y = (p + xc_c * Dv) * (z_c * sig);
            g_y16[(size_t)(base + i) * DI + d] = __float2half(y);
        }
    }
}

// ---------------- launch ------------------------------------------------------
extern "C" void kernel_launch(void* const* d_in, const int* in_sizes, int n_in,
                              void* d_out, int out_size)
{
    const float* x      = (const float*)d_in[0];
    const float* W_in   = (const float*)d_in[1];
    const float* W_conv = (const float*)d_in[2];
    const float* b_conv = (const float*)d_in[3];
    const float* W_x    = (const float*)d_in[4];
    const float* W_dt   = (const float*)d_in[5];
    const float* b_dt   = (const float*)d_in[6];
    const float* A_log  = (const float*)d_in[7];
    const float* Dp     = (const float*)d_in[8];
    const float* W_out  = (const float*)d_in[9];
    float* out = (float*)d_out;

    const int smem_bytes = STAGES * (ATB + BTB);   // 98304
    cudaFuncSetAttribute(gemm_f16<1>, cudaFuncAttributeMaxDynamicSharedMemorySize, smem_bytes);
    cudaFuncSetAttribute(gemm_f16<2>, cudaFuncAttributeMaxDynamicSharedMemorySize, smem_bytes);
    cudaFuncSetAttribute(gemm_f16<3>, cudaFuncAttributeMaxDynamicSharedMemorySize, smem_bytes);

    // 0) fp32 -> fp16 casts
    cvt16<0><<<(ML * DM) / 1024, 256>>>(x);
    cvt16<1><<<(DM * 2 * DI) / 1024, 256>>>(W_in);
    cvt16<2><<<(DI * DI) / 1024, 256>>>(W_dt);
    cvt16<3><<<(DI * DM) / 1024, 256>>>(W_out);

    // 1) xz = x @ W_in -> split g_xin / g_z
    gemm_f16<1><<<dim3(2 * DI / 128, ML / 128), 256, smem_bytes>>>(nullptr, nullptr,
                                                                   2 * DI, DM);
    // 2) depthwise causal conv + SiLU (also writes fp16 xc)
    conv_kernel<<<(ML * DI) / 256, 256>>>(W_conv, b_conv);
    // 3) BC = xc @ W_x
    bc_kernel<<<ML / 32, 256>>>(W_x);
    // 4) dt = softplus(xc @ W_dt + b_dt)
    gemm_f16<2><<<dim3(DI / 128, ML / 128), 256, smem_bytes>>>(nullptr, b_dt,
                                                               DI, DI);
    // 5) chunked selective scan (writes fp16 y)
    scanA_kernel<<<(GSEG * BB * DI) / 8, 128>>>(A_log);
    scanB_kernel<<<(BB * DI * DS) / 256, 256>>>();
    scanC_kernel<<<(GSEG * BB * DI) / 8, 128>>>(A_log, Dp);
    // 6) out = y @ W_out
    gemm_f16<3><<<dim3(DM / 128, ML / 128), 256, smem_bytes>>>(out, nullptr,
                                                               DM, DI);
}

// round 9
// speedup vs baseline: 4.6298x; 1.0368x over previous
#include <cuda_runtime.h>
#include <cuda_fp16.h>

// Problem constants (fixed by the reference)
#define BB 2
#define LL 2048
#define DM 768
#define DI 1536
#define DS 16
#define DC 4
#define ML (BB*LL)          // 4096 rows
#define GSEG 32             // scan segments
#define LC (LL/GSEG)        // 64 steps per segment

// ---------------- scratch (device globals; no allocs allowed) ----------------
__device__ float  g_xin[ML*DI];
__device__ float  g_z  [ML*DI];
__device__ float  g_xc [ML*DI];
__device__ float2 g_BC [ML*DS];    // {B, C} packed
__device__ float2 g_dx [ML*DI];    // {dt, xc} packed
__device__ float  g_h0 [GSEG*BB*DI*DS];
__device__ float  g_P  [GSEG*BB*DI*DS];
__device__ float  g_hin[GSEG*BB*DI*DS];
// fp16 operands (original layouts)
__device__ __align__(16) __half g_x16  [ML*DM];
__device__ __align__(16) __half g_xc16 [ML*DI];
__device__ __align__(16) __half g_y16  [ML*DI];
__device__ __align__(16) __half g_win16[ML > 0 ? DM*2*DI : 1];
__device__ __align__(16) __half g_wdt16[DI*DI];
__device__ __align__(16) __half g_wout16[DI*DM];

// ---------------- helpers -----------------------------------------------------
__device__ __forceinline__ unsigned s2u(const void* p) {
    return (unsigned)__cvta_generic_to_shared(p);
}
__device__ __forceinline__ void cp16(unsigned sdst, const void* src) {
    asm volatile("cp.async.cg.shared.global [%0], [%1], 16;" :: "r"(sdst), "l"(src));
}

#define LDSM_X4(r0,r1,r2,r3,addr) \
    asm volatile("ldmatrix.sync.aligned.m8n8.x4.shared.b16 {%0,%1,%2,%3}, [%4];" \
        : "=r"(r0), "=r"(r1), "=r"(r2), "=r"(r3) : "r"(addr))
#define LDSM_X4T(r0,r1,r2,r3,addr) \
    asm volatile("ldmatrix.sync.aligned.m8n8.x4.trans.shared.b16 {%0,%1,%2,%3}, [%4];" \
        : "=r"(r0), "=r"(r1), "=r"(r2), "=r"(r3) : "r"(addr))

__device__ __forceinline__ void mma16816(float* c, const unsigned* a, const unsigned* b)
{
    asm volatile(
        "mma.sync.aligned.m16n8k16.row.col.f32.f16.f16.f32 "
        "{%0,%1,%2,%3}, {%4,%5,%6,%7}, {%8,%9}, {%0,%1,%2,%3};"
        : "+f"(c[0]), "+f"(c[1]), "+f"(c[2]), "+f"(c[3])
        : "r"(a[0]), "r"(a[1]), "r"(a[2]), "r"(a[3]), "r"(b[0]), "r"(b[1]));
}

__device__ __forceinline__ float softplusf(float v) {
    return fmaxf(v, 0.f) + log1pf(__expf(-fabsf(v)));
}

// ---------------- fused fp32 -> fp16 casts ------------------------------------
#define N0 (ML*DM/4)
#define N1 (DM*2*DI/4)
#define N2 (DI*DI/4)
#define N3 (DI*DM/4)
__global__ void __launch_bounds__(256)
cvt_all(const float* __restrict__ x, const float* __restrict__ win,
        const float* __restrict__ wdt, const float* __restrict__ wout)
{
    const int t = blockIdx.x * 256 + threadIdx.x;
    const float* src; __half* dst; int off;
    if (t < N0)                { src = x;    dst = g_x16;   off = t; }
    else if (t < N0+N1)        { src = win;  dst = g_win16; off = t - N0; }
    else if (t < N0+N1+N2)     { src = wdt;  dst = g_wdt16; off = t - N0 - N1; }
    else if (t < N0+N1+N2+N3)  { src = wout; dst = g_wout16; off = t - N0 - N1 - N2; }
    else return;
    const int i = off * 4;
    float4 v = *(const float4*)&src[i];
    __half2* d2 = (__half2*)&dst[i];
    d2[0] = __floats2half2_rn(v.x, v.y);
    d2[1] = __floats2half2_rn(v.z, v.w);
}

// ---------------- fp16 tensor GEMM: 128x128 tile, BK=64, 3-stage cp.async -----
// MODE 1: A=g_x16,  B=g_win16,  out -> split g_xin / g_z  (N=3072, K=768)
// MODE 2: A=g_xc16, B=g_wdt16,  out -> softplus -> g_dx packed (N=1536, K=1536)
// MODE 3: A=g_y16,  B=g_wout16, out -> d_out              (N=768,  K=1536)
#define STAGES 3
#define ATB 16384
#define BTB 16384

template <int MODE>
__global__ void __launch_bounds__(256, 2)
gemm_f16(float* __restrict__ C0, const float* __restrict__ bias, int N, int K)
{
    const __half* __restrict__ A =
        (MODE == 1) ? g_x16 : (MODE == 2) ? g_xc16 : g_y16;
    const __half* __restrict__ B =
        (MODE == 1) ? g_win16 : (MODE == 2) ? g_wdt16 : g_wout16;

    extern __shared__ char sm[];
    char* Asm = sm;
    char* Bsm = sm + STAGES * ATB;

    const int tid  = threadIdx.x;
    const int lane = tid & 31;
    const int warp = tid >> 5;
    const int gid  = lane >> 2;
    const int tig  = lane & 3;
    const int wm   = (warp >> 2) * 64;
    const int wn   = (warp & 3) * 32;

    const int bm = blockIdx.y * 128;
    const int bn = blockIdx.x * 128;
    const int nt = K / 64;

    auto load_tile = [&](int kt, int s) {
        char* as = Asm + s * ATB;
        char* bs = Bsm + s * BTB;
#pragma unroll
        for (int it = 0; it < 4; it++) {
            const int q = tid + it * 256;
            const int r = q >> 3, c = q & 7;
            cp16(s2u(as) + r * 128 + ((c ^ (r & 7)) << 4),
                 A + (size_t)(bm + r) * K + kt + c * 8);
        }
#pragma unroll
        for (int it = 0; it < 4; it++) {
            const int q = tid + it * 256;
            const int r = q >> 4, c = q & 15;
            cp16(s2u(bs) + r * 256 + ((c ^ (r & 7)) << 4),
                 B + (size_t)(kt + r) * N + bn + c * 8);
        }
    };

    load_tile(0, 0);
    asm volatile("cp.async.commit_group;");
    load_tile(64, 1);
    asm volatile("cp.async.commit_group;");

    float acc[4][4][4];
#pragma unroll
    for (int i = 0; i < 4; i++)
#pragma unroll
        for (int j = 0; j < 4; j++)
#pragma unroll
            for (int q = 0; q < 4; q++) acc[i][j][q] = 0.f;

    for (int i = 0; i < nt; i++) {
        asm volatile("cp.async.wait_group 1;");
        __syncthreads();

        if (i + 2 < nt) load_tile((i + 2) * 64, (i + 2) % STAGES);
        asm volatile("cp.async.commit_group;");

        const unsigned asb = s2u(Asm + (i % STAGES) * ATB);
        const unsigned bsb = s2u(Bsm + (i % STAGES) * BTB);

#pragma unroll
        for (int ks = 0; ks < 4; ks++) {
            unsigned af[4][4];
#pragma unroll
            for (int mt = 0; mt < 4; mt++) {
                const int row = wm + mt * 16 + (lane & 15);
                const unsigned ad = asb + row * 128
                                  + (((2 * ks + (lane >> 4)) ^ (row & 7)) << 4);
                LDSM_X4(af[mt][0], af[mt][1], af[mt][2], af[mt][3], ad);
            }
            unsigned bf[4][2];
#pragma unroll
            for (int p = 0; p < 2; p++) {
                const int krow = ks * 16 + (lane & 15);
                const int nch = (wn >> 3) + p * 2 + (lane >> 4);
                const unsigned bd = bsb + krow * 256 + ((nch ^ (krow & 7)) << 4);
                LDSM_X4T(bf[2 * p][0], bf[2 * p][1], bf[2 * p + 1][0], bf[2 * p + 1][1], bd);
            }
#pragma unroll
            for (int mt = 0; mt < 4; mt++)
#pragma unroll
                for (int nn = 0; nn < 4; nn++)
                    mma16816(acc[mt][nn], af[mt], bf[nn]);
        }
    }

    // ---- vectorized epilogue: (q0,q1)=row r cols c0,c0+1; (q2,q3)=row r+8 ----
#pragma unroll
    for (int mt = 0; mt < 4; mt++) {
#pragma unroll
        for (int nn = 0; nn < 4; nn++) {
            const int c0 = bn + wn + nn * 8 + 2 * tig;
#pragma unroll
            for (int rh = 0; rh < 2; rh++) {
                const int r = bm + wm + mt * 16 + gid + rh * 8;
                const float v0 = acc[mt][nn][rh * 2 + 0];
                const float v1 = acc[mt][nn][rh * 2 + 1];
                if (MODE == 1) {
                    if (c0 < DI)
                        *(float2*)&g_xin[(size_t)r * DI + c0] = make_float2(v0, v1);
                    else
                        *(float2*)&g_z[(size_t)r * DI + (c0 - DI)] = make_float2(v0, v1);
                } else if (MODE == 2) {
                    const float2 bz = *(const float2*)&bias[c0];
                    const float2 xcv = *(const float2*)&g_xc[(size_t)r * DI + c0];
                    float4 st;
                    st.x = softplusf(v0 + bz.x); st.y = xcv.x;
                    st.z = softplusf(v1 + bz.y); st.w = xcv.y;
                    *(float4*)&g_dx[(size_t)r * DI + c0] = st;
                } else {
                    *(float2*)&C0[(size_t)r * DM + c0] = make_float2(v0, v1);
                }
            }
        }
    }
}

// ---------------- depthwise causal conv (k=4) + bias + SiLU -------------------
__global__ void __launch_bounds__(256)
conv_kernel(const float* __restrict__ W_conv, const float* __restrict__ b_conv)
{
    const int idx = blockIdx.x * 256 + threadIdx.x;
    const int d = idx % DI;
    const int t = idx / DI;
    const int l = t % LL;

    float acc = b_conv[d];
#pragma unroll
    for (int j = 0; j < DC; j++) {
        const int ls = l + j - (DC - 1);
        if (ls >= 0)
            acc = fmaf(g_xin[(size_t)(t + j - (DC - 1)) * DI + d], W_conv[d * DC + j], acc);
    }
    const float sig = 1.f / (1.f + __expf(-acc));
    const float v = acc * sig;
    g_xc[idx]   = v;
    g_xc16[idx] = __float2half(v);
}

// ---------------- BC = xc @ W_x  -> packed g_BC -------------------------------
__global__ void __launch_bounds__(256)
bc_kernel(const float* __restrict__ W_x)
{
    const int warp = threadIdx.x >> 5;
    const int c = threadIdx.x & 31;
    const int row = (blockIdx.x * 8 + warp) * 4;
    const float* __restrict__ w = W_x + c;
    float a0 = 0.f, a1 = 0.f, a2 = 0.f, a3 = 0.f;
#pragma unroll 2
    for (int k = 0; k < DI; k += 4) {
        const float w0 = w[(k + 0) * 32];
        const float w1 = w[(k + 1) * 32];
        const float w2 = w[(k + 2) * 32];
        const float w3 = w[(k + 3) * 32];
        float4 x0 = *(const float4*)&g_xc[(size_t)(row + 0) * DI + k];
        float4 x1 = *(const float4*)&g_xc[(size_t)(row + 1) * DI + k];
        float4 x2 = *(const float4*)&g_xc[(size_t)(row + 2) * DI + k];
        float4 x3 = *(const float4*)&g_xc[(size_t)(row + 3) * DI + k];
        a0 = fmaf(x0.x, w0, fmaf(x0.y, w1, fmaf(x0.z, w2, fmaf(x0.w, w3, a0))));
        a1 = fmaf(x1.x, w0, fmaf(x1.y, w1, fmaf(x1.z, w2, fmaf(x1.w, w3, a1))));
        a2 = fmaf(x2.x, w0, fmaf(x2.y, w1, fmaf(x2.z, w2, fmaf(x2.w, w3, a2))));
        a3 = fmaf(x3.x, w0, fmaf(x3.y, w1, fmaf(x3.z, w2, fmaf(x3.w, w3, a3))));
    }
    float acc4[4] = {a0, a1, a2, a3};
#pragma unroll
    for (int r = 0; r < 4; r++) {
        const float cv = __shfl_sync(0xffffffffu, acc4[r], (c & 15) + 16);
        if (c < DS)
            g_BC[(size_t)(row + r) * DS + c] = make_float2(acc4[r], cv);
    }
}

// ---------------- chunked selective scan --------------------------------------
__global__ void __launch_bounds__(128)
scanA_kernel(const float* __restrict__ A_log)
{
    const int grp = threadIdx.x >> 4;
    const int n   = threadIdx.x & 15;
    const int idx = blockIdx.x * 8 + grp;    // (g*BB+b)*DI + d
    const int d   = idx % DI;
    const int t   = idx / DI;
    const int b   = t % BB;
    const int g   = t / BB;

    const float a = -__expf(A_log[d * DS + n]);
    float h = 0.f, sdt = 0.f;
    const int base = b * LL + g * LC;

    float2 dx = g_dx[(size_t)base * DI + d];
    float  Bn = g_BC[(size_t)base * DS + n].x;

    for (int i = 0; i < LC; i++) {
        const float2 dxc = dx;
        const float  B_c = Bn;
        if (i + 1 < LC) {
            const int rb = base + i + 1;
            dx = g_dx[(size_t)rb * DI + d];
            Bn = g_BC[(size_t)rb * DS + n].x;
        }
        h = fmaf(__expf(dxc.x * a), h, dxc.x * B_c * dxc.y);
        sdt += dxc.x;
    }
    g_h0[(size_t)idx * DS + n] = h;
    g_P [(size_t)idx * DS + n] = __expf(a * sdt);
}

__global__ void __launch_bounds__(256)
scanB_kernel()
{
    const int i = blockIdx.x * 256 + threadIdx.x;   // over BB*DI*DS
    const int n = i & 15;
    const int r = i >> 4;
    const int d = r % DI;
    const int b = r / DI;

    float h = 0.f;
#pragma unroll
    for (int g = 0; g < GSEG; g++) {
        const size_t j = (size_t)(((g * BB + b) * DI) + d) * DS + n;
        g_hin[j] = h;
        h = fmaf(g_P[j], h, g_h0[j]);
    }
}

__global__ void __launch_bounds__(128)
scanC_kernel(const float* __restrict__ A_log, const float* __restrict__ Dp)
{
    const int grp = threadIdx.x >> 4;
    const int n   = threadIdx.x & 15;
    const int idx = blockIdx.x * 8 + grp;
    const int d   = idx % DI;
    const int t   = idx / DI;
    const int b   = t % BB;
    const int g   = t / BB;

    const float a  = -__expf(A_log[d * DS + n]);
    const float Dv = Dp[d];
    float h = g_hin[(size_t)idx * DS + n];
    const int base = b * LL + g * LC;

    float2 dx = g_dx[(size_t)base * DI + d];
    float2 bc = g_BC[(size_t)base * DS + n];
    float  zv = (n == 0) ? g_z[(size_t)base * DI + d] : 0.f;

    for (int i = 0; i < LC; i++) {
        const float2 dxc = dx;
        const float2 bcc = bc;
        const float  z_c = zv;
        if (i + 1 < LC) {
            const int rb = base + i + 1;
            dx = g_dx[(size_t)rb * DI + d];
            bc = g_BC[(size_t)rb * DS + n];
            if (n == 0) zv = g_z[(size_t)rb * DI + d];
        }

        h = fmaf(__expf(dxc.x * a), h, dxc.x * bcc.x * dxc.y);

        float p = h * bcc.y;
        p += __shfl_xor_sync(0xffffffffu, p, 8);
        p += __shfl_xor_sync(0xffffffffu, p, 4);
        p += __shfl_xor_sync(0xffffffffu, p, 2);
        p += __shfl_xor_sync(0xffffffffu, p, 1);

        if (n == 0) {
            const float sig = 1.f / (1.f + __expf(-z_c));
            const float y = (p + dxc.y * Dv) * (z_c * sig);
            g_y16[(size_t)(base + i) * DI + d] = __float2half(y);
        }
    }
}

// ---------------- launch ------------------------------------------------------
extern "C" void kernel_launch(void* const* d_in, const int* in_sizes, int n_in,
                              void* d_out, int out_size)
{
    const float* x      = (const float*)d_in[0];
    const float* W_in   = (const float*)d_in[1];
    const float* W_conv = (const float*)d_in[2];
    const float* b_conv = (const float*)d_in[3];
    const float* W_x    = (const float*)d_in[4];
    const float* W_dt   = (const float*)d_in[5];
    const float* b_dt   = (const float*)d_in[6];
    const float* A_log  = (const float*)d_in[7];
    const float* Dp     = (const float*)d_in[8];
    const float* W_out  = (const float*)d_in[9];
    float* out = (float*)d_out;

    const int smem_bytes = STAGES * (ATB + BTB);   // 98304
    cudaFuncSetAttribute(gemm_f16<1>, cudaFuncAttributeMaxDynamicSharedMemorySize, smem_bytes);
    cudaFuncSetAttribute(gemm_f16<2>, cudaFuncAttributeMaxDynamicSharedMemorySize, smem_bytes);
    cudaFuncSetAttribute(gemm_f16<3>, cudaFuncAttributeMaxDynamicSharedMemorySize, smem_bytes);

    // 0) fused fp32 -> fp16 casts
    const int ctot = N0 + N1 + N2 + N3;
    cvt_all<<<(ctot + 255) / 256, 256>>>(x, W_in, W_dt, W_out);

    // 1) xz = x @ W_in -> split g_xin / g_z
    gemm_f16<1><<<dim3(2 * DI / 128, ML / 128), 256, smem_bytes>>>(nullptr, nullptr,
                                                                   2 * DI, DM);
    // 2) depthwise causal conv + SiLU
    conv_kernel<<<(ML * DI) / 256, 256>>>(W_conv, b_conv);
    // 3) BC = xc @ W_x -> packed
    bc_kernel<<<ML / 32, 256>>>(W_x);
    // 4) dt = softplus(xc @ W_dt + b_dt) -> packed {dt, xc}
    gemm_f16<2><<<dim3(DI / 128, ML / 128), 256, smem_bytes>>>(nullptr, b_dt,
                                                               DI, DI);
    // 5) chunked selective scan
    scanA_kernel<<<(GSEG * BB * DI) / 8, 128>>>(A_log);
    scanB_kernel<<<(BB * DI * DS) / 256, 256>>>();
    scanC_kernel<<<(GSEG * BB * DI) / 8, 128>>>(A_log, Dp);
    // 6) out = y @ W_out
    gemm_f16<3><<<dim3(DM / 128, ML / 128), 256, smem_bytes>>>(out, nullptr,
                                                               DM, DI);
}

// round 11
// speedup vs baseline: 5.9084x; 1.2762x over previous
#include <cuda_runtime.h>
#include <cuda_fp16.h>

// Problem constants (fixed by the reference)
#define BB 2
#define LL 2048
#define DM 768
#define DI 1536
#define DS 16
#define DC 4
#define ML (BB*LL)          // 4096 rows
#define GSEG 32             // scan segments
#define LC (LL/GSEG)        // 64 steps per segment
#define KSPL 4              // bc split-K factor
#define KCH (DI/KSPL)       // 384

// ---------------- scratch (device globals; no allocs allowed) ----------------
__device__ float  g_xin[ML*DI];
__device__ float  g_z  [ML*DI];
__device__ float  g_xc [ML*DI];
__device__ float2 g_BC [ML*DS];    // {B, C} packed
__device__ float2 g_dx [ML*DI];    // {dt, xc} packed
__device__ float  g_bcp[KSPL*ML*32];   // bc split-K partials
__device__ float  g_h0 [GSEG*BB*DI*DS];
__device__ float  g_P  [GSEG*BB*DI*DS];
__device__ float  g_hin[GSEG*BB*DI*DS];
// fp16 operands (original layouts)
__device__ __align__(16) __half g_x16  [ML*DM];
__device__ __align__(16) __half g_xc16 [ML*DI];
__device__ __align__(16) __half g_y16  [ML*DI];
__device__ __align__(16) __half g_win16[DM*2*DI];
__device__ __align__(16) __half g_wdt16[DI*DI];
__device__ __align__(16) __half g_wout16[DI*DM];

// ---------------- helpers -----------------------------------------------------
__device__ __forceinline__ unsigned s2u(const void* p) {
    return (unsigned)__cvta_generic_to_shared(p);
}
__device__ __forceinline__ void cp16(unsigned sdst, const void* src) {
    asm volatile("cp.async.cg.shared.global [%0], [%1], 16;" :: "r"(sdst), "l"(src));
}

#define LDSM_X4(r0,r1,r2,r3,addr) \
    asm volatile("ldmatrix.sync.aligned.m8n8.x4.shared.b16 {%0,%1,%2,%3}, [%4];" \
        : "=r"(r0), "=r"(r1), "=r"(r2), "=r"(r3) : "r"(addr))
#define LDSM_X4T(r0,r1,r2,r3,addr) \
    asm volatile("ldmatrix.sync.aligned.m8n8.x4.trans.shared.b16 {%0,%1,%2,%3}, [%4];" \
        : "=r"(r0), "=r"(r1), "=r"(r2), "=r"(r3) : "r"(addr))

__device__ __forceinline__ void mma16816(float* c, const unsigned* a, const unsigned* b)
{
    asm volatile(
        "mma.sync.aligned.m16n8k16.row.col.f32.f16.f16.f32 "
        "{%0,%1,%2,%3}, {%4,%5,%6,%7}, {%8,%9}, {%0,%1,%2,%3};"
        : "+f"(c[0]), "+f"(c[1]), "+f"(c[2]), "+f"(c[3])
        : "r"(a[0]), "r"(a[1]), "r"(a[2]), "r"(a[3]), "r"(b[0]), "r"(b[1]));
}

__device__ __forceinline__ float softplusf(float v) {
    return fmaxf(v, 0.f) + log1pf(__expf(-fabsf(v)));
}

// ---------------- fused fp32 -> fp16 casts ------------------------------------
#define N0 (ML*DM/4)
#define N1 (DM*2*DI/4)
#define N2 (DI*DI/4)
#define N3 (DI*DM/4)
__global__ void __launch_bounds__(256)
cvt_all(const float* __restrict__ x, const float* __restrict__ win,
        const float* __restrict__ wdt, const float* __restrict__ wout)
{
    const int t = blockIdx.x * 256 + threadIdx.x;
    const float* src; __half* dst; int off;
    if (t < N0)                { src = x;    dst = g_x16;   off = t; }
    else if (t < N0+N1)        { src = win;  dst = g_win16; off = t - N0; }
    else if (t < N0+N1+N2)     { src = wdt;  dst = g_wdt16; off = t - N0 - N1; }
    else if (t < N0+N1+N2+N3)  { src = wout; dst = g_wout16; off = t - N0 - N1 - N2; }
    else return;
    const int i = off * 4;
    float4 v = *(const float4*)&src[i];
    __half2* d2 = (__half2*)&dst[i];
    d2[0] = __floats2half2_rn(v.x, v.y);
    d2[1] = __floats2half2_rn(v.z, v.w);
}

// ---------------- fp16 tensor GEMM: 128x128 tile, BK=64, 3-stage cp.async -----
// MODE 1: A=g_x16,  B=g_win16,  out -> split g_xin / g_z  (N=3072, K=768)
// MODE 2: A=g_xc16, B=g_wdt16,  out -> softplus -> g_dx packed (N=1536, K=1536)
// MODE 3: A=g_y16,  B=g_wout16, out -> d_out              (N=768,  K=1536)
#define STAGES 3
#define ATB 16384
#define BTB 16384

template <int MODE>
__global__ void __launch_bounds__(256, 2)
gemm_f16(float* __restrict__ C0, const float* __restrict__ bias, int N, int K)
{
    const __half* __restrict__ A =
        (MODE == 1) ? g_x16 : (MODE == 2) ? g_xc16 : g_y16;
    const __half* __restrict__ B =
        (MODE == 1) ? g_win16 : (MODE == 2) ? g_wdt16 : g_wout16;

    extern __shared__ char sm[];
    char* Asm = sm;
    char* Bsm = sm + STAGES * ATB;

    const int tid  = threadIdx.x;
    const int lane = tid & 31;
    const int warp = tid >> 5;
    const int gid  = lane >> 2;
    const int tig  = lane & 3;
    const int wm   = (warp >> 2) * 64;
    const int wn   = (warp & 3) * 32;

    const int bm = blockIdx.y * 128;
    const int bn = blockIdx.x * 128;
    const int nt = K / 64;

    auto load_tile = [&](int kt, int s) {
        char* as = Asm + s * ATB;
        char* bs = Bsm + s * BTB;
#pragma unroll
        for (int it = 0; it < 4; it++) {
            const int q = tid + it * 256;
            const int r = q >> 3, c = q & 7;
            cp16(s2u(as) + r * 128 + ((c ^ (r & 7)) << 4),
                 A + (size_t)(bm + r) * K + kt + c * 8);
        }
#pragma unroll
        for (int it = 0; it < 4; it++) {
            const int q = tid + it * 256;
            const int r = q >> 4, c = q & 15;
            cp16(s2u(bs) + r * 256 + ((c ^ (r & 7)) << 4),
                 B + (size_t)(kt + r) * N + bn + c * 8);
        }
    };

    load_tile(0, 0);
    asm volatile("cp.async.commit_group;");
    load_tile(64, 1);
    asm volatile("cp.async.commit_group;");

    float acc[4][4][4];
#pragma unroll
    for (int i = 0; i < 4; i++)
#pragma unroll
        for (int j = 0; j < 4; j++)
#pragma unroll
            for (int q = 0; q < 4; q++) acc[i][j][q] = 0.f;

    for (int i = 0; i < nt; i++) {
        asm volatile("cp.async.wait_group 1;");
        __syncthreads();

        if (i + 2 < nt) load_tile((i + 2) * 64, (i + 2) % STAGES);
        asm volatile("cp.async.commit_group;");

        const unsigned asb = s2u(Asm + (i % STAGES) * ATB);
        const unsigned bsb = s2u(Bsm + (i % STAGES) * BTB);

#pragma unroll
        for (int ks = 0; ks < 4; ks++) {
            unsigned af[4][4];
#pragma unroll
            for (int mt = 0; mt < 4; mt++) {
                const int row = wm + mt * 16 + (lane & 15);
                const unsigned ad = asb + row * 128
                                  + (((2 * ks + (lane >> 4)) ^ (row & 7)) << 4);
                LDSM_X4(af[mt][0], af[mt][1], af[mt][2], af[mt][3], ad);
            }
            unsigned bf[4][2];
#pragma unroll
            for (int p = 0; p < 2; p++) {
                const int krow = ks * 16 + (lane & 15);
                const int nch = (wn >> 3) + p * 2 + (lane >> 4);
                const unsigned bd = bsb + krow * 256 + ((nch ^ (krow & 7)) << 4);
                LDSM_X4T(bf[2 * p][0], bf[2 * p][1], bf[2 * p + 1][0], bf[2 * p + 1][1], bd);
            }
#pragma unroll
            for (int mt = 0; mt < 4; mt++)
#pragma unroll
                for (int nn = 0; nn < 4; nn++)
                    mma16816(acc[mt][nn], af[mt], bf[nn]);
        }
    }

    // ---- vectorized epilogue ----
#pragma unroll
    for (int mt = 0; mt < 4; mt++) {
#pragma unroll
        for (int nn = 0; nn < 4; nn++) {
            const int c0 = bn + wn + nn * 8 + 2 * tig;
#pragma unroll
            for (int rh = 0; rh < 2; rh++) {
                const int r = bm + wm + mt * 16 + gid + rh * 8;
                const float v0 = acc[mt][nn][rh * 2 + 0];
                const float v1 = acc[mt][nn][rh * 2 + 1];
                if (MODE == 1) {
                    if (c0 < DI)
                        *(float2*)&g_xin[(size_t)r * DI + c0] = make_float2(v0, v1);
                    else
                        *(float2*)&g_z[(size_t)r * DI + (c0 - DI)] = make_float2(v0, v1);
                } else if (MODE == 2) {
                    const float2 bz = *(const float2*)&bias[c0];
                    const float2 xcv = *(const float2*)&g_xc[(size_t)r * DI + c0];
                    float4 st;
                    st.x = softplusf(v0 + bz.x); st.y = xcv.x;
                    st.z = softplusf(v1 + bz.y); st.w = xcv.y;
                    *(float4*)&g_dx[(size_t)r * DI + c0] = st;
                } else {
                    *(float2*)&C0[(size_t)r * DM + c0] = make_float2(v0, v1);
                }
            }
        }
    }
}

// ---------------- depthwise causal conv (k=4) + bias + SiLU -------------------
__global__ void __launch_bounds__(256)
conv_kernel(const float* __restrict__ W_conv, const float* __restrict__ b_conv)
{
    const int idx = blockIdx.x * 256 + threadIdx.x;
    const int d = idx % DI;
    const int t = idx / DI;
    const int l = t % LL;

    float acc = b_conv[d];
#pragma unroll
    for (int j = 0; j < DC; j++) {
        const int ls = l + j - (DC - 1);
        if (ls >= 0)
            acc = fmaf(g_xin[(size_t)(t + j - (DC - 1)) * DI + d], W_conv[d * DC + j], acc);
    }
    const float sig = 1.f / (1.f + __expf(-acc));
    const float v = acc * sig;
    g_xc[idx]   = v;
    g_xc16[idx] = __float2half(v);
}

// ---------------- BC = xc @ W_x : split-K partials ----------------------------
// warp -> (4 rows, K/4 chunk). grid = ML/4 * KSPL / 8 warps = 512 blocks.
__global__ void __launch_bounds__(256)
bc_partial(const float* __restrict__ W_x)
{
    const int gw  = blockIdx.x * 8 + (threadIdx.x >> 5);  // global warp id
    const int c   = threadIdx.x & 31;
    const int rg  = gw >> 2;            // row group 0..1023
    const int ks  = gw & 3;             // k-split 0..3
    const int row = rg * 4;
    const int k0  = ks * KCH;

    const float* __restrict__ w = W_x + c;
    float a0 = 0.f, a1 = 0.f, a2 = 0.f, a3 = 0.f;
#pragma unroll 4
    for (int k = k0; k < k0 + KCH; k += 4) {
        const float w0 = w[(k + 0) * 32];
        const float w1 = w[(k + 1) * 32];
        const float w2 = w[(k + 2) * 32];
        const float w3 = w[(k + 3) * 32];
        float4 x0 = *(const float4*)&g_xc[(size_t)(row + 0) * DI + k];
        float4 x1 = *(const float4*)&g_xc[(size_t)(row + 1) * DI + k];
        float4 x2 = *(const float4*)&g_xc[(size_t)(row + 2) * DI + k];
        float4 x3 = *(const float4*)&g_xc[(size_t)(row + 3) * DI + k];
        a0 = fmaf(x0.x, w0, fmaf(x0.y, w1, fmaf(x0.z, w2, fmaf(x0.w, w3, a0))));
        a1 = fmaf(x1.x, w0, fmaf(x1.y, w1, fmaf(x1.z, w2, fmaf(x1.w, w3, a1))));
        a2 = fmaf(x2.x, w0, fmaf(x2.y, w1, fmaf(x2.z, w2, fmaf(x2.w, w3, a2))));
        a3 = fmaf(x3.x, w0, fmaf(x3.y, w1, fmaf(x3.z, w2, fmaf(x3.w, w3, a3))));
    }
    float acc4[4] = {a0, a1, a2, a3};
#pragma unroll
    for (int r = 0; r < 4; r++)
        g_bcp[((size_t)ks * ML + (row + r)) * 32 + c] = acc4[r];
}

// reduce partials -> packed float2 {B, C}
__global__ void __launch_bounds__(256)
bc_pack()
{
    const int t = blockIdx.x * 256 + threadIdx.x;   // over ML*DS
    const int row = t >> 4;
    const int n   = t & 15;
    float B = 0.f, C = 0.f;
#pragma unroll
    for (int ks = 0; ks < KSPL; ks++) {
        B += g_bcp[((size_t)ks * ML + row) * 32 + n];
        C += g_bcp[((size_t)ks * ML + row) * 32 + 16 + n];
    }
    g_BC[(size_t)row * DS + n] = make_float2(B, C);
}

// ---------------- chunked selective scan --------------------------------------
__global__ void __launch_bounds__(128)
scanA_kernel(const float* __restrict__ A_log)
{
    const int grp = threadIdx.x >> 4;
    const int n   = threadIdx.x & 15;
    const int idx = blockIdx.x * 8 + grp;    // (g*BB+b)*DI + d
    const int d   = idx % DI;
    const int t   = idx / DI;
    const int b   = t % BB;
    const int g   = t / BB;

    const float a = -__expf(A_log[d * DS + n]);
    float h = 0.f, sdt = 0.f;
    const int base = b * LL + g * LC;

    float2 dx = g_dx[(size_t)base * DI + d];
    float  Bn = g_BC[(size_t)base * DS + n].x;

    for (int i = 0; i < LC; i++) {
        const float2 dxc = dx;
        const float  B_c = Bn;
        if (i + 1 < LC) {
            const int rb = base + i + 1;
            dx = g_dx[(size_t)rb * DI + d];
            Bn = g_BC[(size_t)rb * DS + n].x;
        }
        h = fmaf(__expf(dxc.x * a), h, dxc.x * B_c * dxc.y);
        sdt += dxc.x;
    }
    g_h0[(size_t)idx * DS + n] = h;
    g_P [(size_t)idx * DS + n] = __expf(a * sdt);
}

__global__ void __launch_bounds__(256)
scanB_kernel()
{
    const int i = blockIdx.x * 256 + threadIdx.x;   // over BB*DI*DS
    const int n = i & 15;
    const int r = i >> 4;
    const int d = r % DI;
    const int b = r / DI;

    float h = 0.f;
#pragma unroll
    for (int g = 0; g < GSEG; g++) {
        const size_t j = (size_t)(((g * BB + b) * DI) + d) * DS + n;
        g_hin[j] = h;
        h = fmaf(g_P[j], h, g_h0[j]);
    }
}

__global__ void __launch_bounds__(128)
scanC_kernel(const float* __restrict__ A_log, const float* __restrict__ Dp)
{
    const int grp = threadIdx.x >> 4;
    const int n   = threadIdx.x & 15;
    const int idx = blockIdx.x * 8 + grp;
    const int d   = idx % DI;
    const int t   = idx / DI;
    const int b   = t % BB;
    const int g   = t / BB;

    const float a  = -__expf(A_log[d * DS + n]);
    const float Dv = Dp[d];
    float h = g_hin[(size_t)idx * DS + n];
    const int base = b * LL + g * LC;

    float2 dx = g_dx[(size_t)base * DI + d];
    float2 bc = g_BC[(size_t)base * DS + n];
    float  zv = (n == 0) ? g_z[(size_t)base * DI + d] : 0.f;

    for (int i = 0; i < LC; i++) {
        const float2 dxc = dx;
        const float2 bcc = bc;
        const float  z_c = zv;
        if (i + 1 < LC) {
            const int rb = base + i + 1;
            dx = g_dx[(size_t)rb * DI + d];
            bc = g_BC[(size_t)rb * DS + n];
            if (n == 0) zv = g_z[(size_t)rb * DI + d];
        }

        h = fmaf(__expf(dxc.x * a), h, dxc.x * bcc.x * dxc.y);

        float p = h * bcc.y;
        p += __shfl_xor_sync(0xffffffffu, p, 8);
        p += __shfl_xor_sync(0xffffffffu, p, 4);
        p += __shfl_xor_sync(0xffffffffu, p, 2);
        p += __shfl_xor_sync(0xffffffffu, p, 1);

        if (n == 0) {
            const float sig = 1.f / (1.f + __expf(-z_c));
            const float y = (p + dxc.y * Dv) * (z_c * sig);
            g_y16[(size_t)(base + i) * DI + d] = __float2half(y);
        }
    }
}

// ---------------- launch ------------------------------------------------------
extern "C" void kernel_launch(void* const* d_in, const int* in_sizes, int n_in,
                              void* d_out, int out_size)
{
    const float* x      = (const float*)d_in[0];
    const float* W_in   = (const float*)d_in[1];
    const float* W_conv = (const float*)d_in[2];
    const float* b_conv = (const float*)d_in[3];
    const float* W_x    = (const float*)d_in[4];
    const float* W_dt   = (const float*)d_in[5];
    const float* b_dt   = (const float*)d_in[6];
    const float* A_log  = (const float*)d_in[7];
    const float* Dp     = (const float*)d_in[8];
    const float* W_out  = (const float*)d_in[9];
    float* out = (float*)d_out;

    const int smem_bytes = STAGES * (ATB + BTB);   // 98304
    cudaFuncSetAttribute(gemm_f16<1>, cudaFuncAttributeMaxDynamicSharedMemorySize, smem_bytes);
    cudaFuncSetAttribute(gemm_f16<2>, cudaFuncAttributeMaxDynamicSharedMemorySize, smem_bytes);
    cudaFuncSetAttribute(gemm_f16<3>, cudaFuncAttributeMaxDynamicSharedMemorySize, smem_bytes);

    // 0) fused fp32 -> fp16 casts
    const int ctot = N0 + N1 + N2 + N3;
    cvt_all<<<(ctot + 255) / 256, 256>>>(x, W_in, W_dt, W_out);

    // 1) xz = x @ W_in -> split g_xin / g_z
    gemm_f16<1><<<dim3(2 * DI / 128, ML / 128), 256, smem_bytes>>>(nullptr, nullptr,
                                                                   2 * DI, DM);
    // 2) depthwise causal conv + SiLU
    conv_kernel<<<(ML * DI) / 256, 256>>>(W_conv, b_conv);
    // 3) BC = xc @ W_x -> split-K partials + pack
    bc_partial<<<(ML / 4) * KSPL / 8, 256>>>(W_x);
    bc_pack<<<(ML * DS) / 256, 256>>>();
    // 4) dt = softplus(xc @ W_dt + b_dt) -> packed {dt, xc}
    gemm_f16<2><<<dim3(DI / 128, ML / 128), 256, smem_bytes>>>(nullptr, b_dt,
                                                               DI, DI);
    // 5) chunked selective scan
    scanA_kernel<<<(GSEG * BB * DI) / 8, 128>>>(A_log);
    scanB_kernel<<<(BB * DI * DS) / 256, 256>>>();
    scanC_kernel<<<(GSEG * BB * DI) / 8, 128>>>(A_log, Dp);
    // 6) out = y @ W_out
    gemm_f16<3><<<dim3(DM / 128, ML / 128), 256, smem_bytes>>>(out, nullptr,
                                                               DM, DI);
}

// round 12
// speedup vs baseline: 7.1478x; 1.2098x over previous
#include <cuda_runtime.h>
#include <cuda_fp16.h>

// Problem constants (fixed by the reference)
#define BB 2
#define LL 2048
#define DM 768
#define DI 1536
#define DS 16
#define DC 4
#define ML (BB*LL)          // 4096 rows
#define GSEG 32             // scan segments
#define LC (LL/GSEG)        // 64 steps per segment
#define KSPL 8              // bc split-K factor
#define KCH (DI/KSPL)       // 192

// ---------------- scratch (device globals; no allocs allowed) ----------------
__device__ float  g_xin[ML*DI];
__device__ float  g_z  [ML*DI];
__device__ float  g_xc [ML*DI];
__device__ float4 g_BC2[ML*8];     // [t][j]: {B_j, C_j, B_{j+8}, C_{j+8}}
__device__ float4 g_dx [ML*DI];    // {dt, xc, z, 0} packed
__device__ float  g_bcp[KSPL*ML*32];   // bc split-K partials
__device__ float  g_h0 [GSEG*BB*DI*DS];
__device__ float  g_P  [GSEG*BB*DI*DS];
__device__ float  g_hin[GSEG*BB*DI*DS];
// fp16 operands (original layouts)
__device__ __align__(16) __half g_x16  [ML*DM];
__device__ __align__(16) __half g_xc16 [ML*DI];
__device__ __align__(16) __half g_y16  [ML*DI];
__device__ __align__(16) __half g_win16[DM*2*DI];
__device__ __align__(16) __half g_wdt16[DI*DI];
__device__ __align__(16) __half g_wout16[DI*DM];

// ---------------- helpers -----------------------------------------------------
__device__ __forceinline__ unsigned s2u(const void* p) {
    return (unsigned)__cvta_generic_to_shared(p);
}
__device__ __forceinline__ void cp16(unsigned sdst, const void* src) {
    asm volatile("cp.async.cg.shared.global [%0], [%1], 16;" :: "r"(sdst), "l"(src));
}

#define LDSM_X4(r0,r1,r2,r3,addr) \
    asm volatile("ldmatrix.sync.aligned.m8n8.x4.shared.b16 {%0,%1,%2,%3}, [%4];" \
        : "=r"(r0), "=r"(r1), "=r"(r2), "=r"(r3) : "r"(addr))
#define LDSM_X4T(r0,r1,r2,r3,addr) \
    asm volatile("ldmatrix.sync.aligned.m8n8.x4.trans.shared.b16 {%0,%1,%2,%3}, [%4];" \
        : "=r"(r0), "=r"(r1), "=r"(r2), "=r"(r3) : "r"(addr))

__device__ __forceinline__ void mma16816(float* c, const unsigned* a, const unsigned* b)
{
    asm volatile(
        "mma.sync.aligned.m16n8k16.row.col.f32.f16.f16.f32 "
        "{%0,%1,%2,%3}, {%4,%5,%6,%7}, {%8,%9}, {%0,%1,%2,%3};"
        : "+f"(c[0]), "+f"(c[1]), "+f"(c[2]), "+f"(c[3])
        : "r"(a[0]), "r"(a[1]), "r"(a[2]), "r"(a[3]), "r"(b[0]), "r"(b[1]));
}

__device__ __forceinline__ float softplusf(float v) {
    return fmaxf(v, 0.f) + log1pf(__expf(-fabsf(v)));
}

// ---------------- fused fp32 -> fp16 casts ------------------------------------
#define N0 (ML*DM/4)
#define N1 (DM*2*DI/4)
#define N2 (DI*DI/4)
#define N3 (DI*DM/4)
__global__ void __launch_bounds__(256)
cvt_all(const float* __restrict__ x, const float* __restrict__ win,
        const float* __restrict__ wdt, const float* __restrict__ wout)
{
    const int t = blockIdx.x * 256 + threadIdx.x;
    const float* src; __half* dst; int off;
    if (t < N0)                { src = x;    dst = g_x16;   off = t; }
    else if (t < N0+N1)        { src = win;  dst = g_win16; off = t - N0; }
    else if (t < N0+N1+N2)     { src = wdt;  dst = g_wdt16; off = t - N0 - N1; }
    else if (t < N0+N1+N2+N3)  { src = wout; dst = g_wout16; off = t - N0 - N1 - N2; }
    else return;
    const int i = off * 4;
    float4 v = *(const float4*)&src[i];
    __half2* d2 = (__half2*)&dst[i];
    d2[0] = __floats2half2_rn(v.x, v.y);
    d2[1] = __floats2half2_rn(v.z, v.w);
}

// ---------------- fp16 tensor GEMM: 128x128 tile, BK=64, 3-stage cp.async -----
// MODE 1: A=g_x16,  B=g_win16,  out -> split g_xin / g_z  (N=3072, K=768)
// MODE 2: A=g_xc16, B=g_wdt16,  out -> {softplus, xc, z} -> g_dx (N=1536, K=1536)
// MODE 3: A=g_y16,  B=g_wout16, out -> d_out              (N=768,  K=1536)
#define STAGES 3
#define ATB 16384
#define BTB 16384

template <int MODE>
__global__ void __launch_bounds__(256, 2)
gemm_f16(float* __restrict__ C0, const float* __restrict__ bias, int N, int K)
{
    const __half* __restrict__ A =
        (MODE == 1) ? g_x16 : (MODE == 2) ? g_xc16 : g_y16;
    const __half* __restrict__ B =
        (MODE == 1) ? g_win16 : (MODE == 2) ? g_wdt16 : g_wout16;

    extern __shared__ char sm[];
    char* Asm = sm;
    char* Bsm = sm + STAGES * ATB;

    const int tid  = threadIdx.x;
    const int lane = tid & 31;
    const int warp = tid >> 5;
    const int gid  = lane >> 2;
    const int tig  = lane & 3;
    const int wm   = (warp >> 2) * 64;
    const int wn   = (warp & 3) * 32;

    const int bm = blockIdx.y * 128;
    const int bn = blockIdx.x * 128;
    const int nt = K / 64;

    auto load_tile = [&](int kt, int s) {
        char* as = Asm + s * ATB;
        char* bs = Bsm + s * BTB;
#pragma unroll
        for (int it = 0; it < 4; it++) {
            const int q = tid + it * 256;
            const int r = q >> 3, c = q & 7;
            cp16(s2u(as) + r * 128 + ((c ^ (r & 7)) << 4),
                 A + (size_t)(bm + r) * K + kt + c * 8);
        }
#pragma unroll
        for (int it = 0; it < 4; it++) {
            const int q = tid + it * 256;
            const int r = q >> 4, c = q & 15;
            cp16(s2u(bs) + r * 256 + ((c ^ (r & 7)) << 4),
                 B + (size_t)(kt + r) * N + bn + c * 8);
        }
    };

    load_tile(0, 0);
    asm volatile("cp.async.commit_group;");
    load_tile(64, 1);
    asm volatile("cp.async.commit_group;");

    float acc[4][4][4];
#pragma unroll
    for (int i = 0; i < 4; i++)
#pragma unroll
        for (int j = 0; j < 4; j++)
#pragma unroll
            for (int q = 0; q < 4; q++) acc[i][j][q] = 0.f;

    for (int i = 0; i < nt; i++) {
        asm volatile("cp.async.wait_group 1;");
        __syncthreads();

        if (i + 2 < nt) load_tile((i + 2) * 64, (i + 2) % STAGES);
        asm volatile("cp.async.commit_group;");

        const unsigned asb = s2u(Asm + (i % STAGES) * ATB);
        const unsigned bsb = s2u(Bsm + (i % STAGES) * BTB);

#pragma unroll
        for (int ks = 0; ks < 4; ks++) {
            unsigned af[4][4];
#pragma unroll
            for (int mt = 0; mt < 4; mt++) {
                const int row = wm + mt * 16 + (lane & 15);
                const unsigned ad = asb + row * 128
                                  + (((2 * ks + (lane >> 4)) ^ (row & 7)) << 4);
                LDSM_X4(af[mt][0], af[mt][1], af[mt][2], af[mt][3], ad);
            }
            unsigned bf[4][2];
#pragma unroll
            for (int p = 0; p < 2; p++) {
                const int krow = ks * 16 + (lane & 15);
                const int nch = (wn >> 3) + p * 2 + (lane >> 4);
                const unsigned bd = bsb + krow * 256 + ((nch ^ (krow & 7)) << 4);
                LDSM_X4T(bf[2 * p][0], bf[2 * p][1], bf[2 * p + 1][0], bf[2 * p + 1][1], bd);
            }
#pragma unroll
            for (int mt = 0; mt < 4; mt++)
#pragma unroll
                for (int nn = 0; nn < 4; nn++)
                    mma16816(acc[mt][nn], af[mt], bf[nn]);
        }
    }

    // ---- vectorized epilogue ----
#pragma unroll
    for (int mt = 0; mt < 4; mt++) {
#pragma unroll
        for (int nn = 0; nn < 4; nn++) {
            const int c0 = bn + wn + nn * 8 + 2 * tig;
#pragma unroll
            for (int rh = 0; rh < 2; rh++) {
                const int r = bm + wm + mt * 16 + gid + rh * 8;
                const float v0 = acc[mt][nn][rh * 2 + 0];
                const float v1 = acc[mt][nn][rh * 2 + 1];
                if (MODE == 1) {
                    if (c0 < DI)
                        *(float2*)&g_xin[(size_t)r * DI + c0] = make_float2(v0, v1);
                    else
                        *(float2*)&g_z[(size_t)r * DI + (c0 - DI)] = make_float2(v0, v1);
                } else if (MODE == 2) {
                    const float2 bz  = *(const float2*)&bias[c0];
                    const float2 xcv = *(const float2*)&g_xc[(size_t)r * DI + c0];
                    const float2 zv  = *(const float2*)&g_z [(size_t)r * DI + c0];
                    g_dx[(size_t)r * DI + c0]     = make_float4(softplusf(v0 + bz.x), xcv.x, zv.x, 0.f);
                    g_dx[(size_t)r * DI + c0 + 1] = make_float4(softplusf(v1 + bz.y), xcv.y, zv.y, 0.f);
                } else {
                    *(float2*)&C0[(size_t)r * DM + c0] = make_float2(v0, v1);
                }
            }
        }
    }
}

// ---------------- depthwise causal conv (k=4) + bias + SiLU -------------------
__global__ void __launch_bounds__(256)
conv_kernel(const float* __restrict__ W_conv, const float* __restrict__ b_conv)
{
    const int idx = blockIdx.x * 256 + threadIdx.x;
    const int d = idx % DI;
    const int t = idx / DI;
    const int l = t % LL;

    float acc = b_conv[d];
#pragma unroll
    for (int j = 0; j < DC; j++) {
        const int ls = l + j - (DC - 1);
        if (ls >= 0)
            acc = fmaf(g_xin[(size_t)(t + j - (DC - 1)) * DI + d], W_conv[d * DC + j], acc);
    }
    const float sig = 1.f / (1.f + __expf(-acc));
    const float v = acc * sig;
    g_xc[idx]   = v;
    g_xc16[idx] = __float2half(v);
}

// ---------------- BC = xc @ W_x : split-K partials ----------------------------
// warp -> (4 rows, K/8 chunk). grid = ML/4 * KSPL / 8 warps = 1024 blocks.
__global__ void __launch_bounds__(256)
bc_partial(const float* __restrict__ W_x)
{
    const int gw  = blockIdx.x * 8 + (threadIdx.x >> 5);  // global warp id
    const int c   = threadIdx.x & 31;
    const int rg  = gw >> 3;            // row group 0..1023
    const int ks  = gw & 7;             // k-split 0..7
    const int row = rg * 4;
    const int k0  = ks * KCH;

    const float* __restrict__ w = W_x + c;
    float a0 = 0.f, a1 = 0.f, a2 = 0.f, a3 = 0.f;
#pragma unroll 4
    for (int k = k0; k < k0 + KCH; k += 4) {
        const float w0 = w[(k + 0) * 32];
        const float w1 = w[(k + 1) * 32];
        const float w2 = w[(k + 2) * 32];
        const float w3 = w[(k + 3) * 32];
        float4 x0 = *(const float4*)&g_xc[(size_t)(row + 0) * DI + k];
        float4 x1 = *(const float4*)&g_xc[(size_t)(row + 1) * DI + k];
        float4 x2 = *(const float4*)&g_xc[(size_t)(row + 2) * DI + k];
        float4 x3 = *(const float4*)&g_xc[(size_t)(row + 3) * DI + k];
        a0 = fmaf(x0.x, w0, fmaf(x0.y, w1, fmaf(x0.z, w2, fmaf(x0.w, w3, a0))));
        a1 = fmaf(x1.x, w0, fmaf(x1.y, w1, fmaf(x1.z, w2, fmaf(x1.w, w3, a1))));
        a2 = fmaf(x2.x, w0, fmaf(x2.y, w1, fmaf(x2.z, w2, fmaf(x2.w, w3, a2))));
        a3 = fmaf(x3.x, w0, fmaf(x3.y, w1, fmaf(x3.z, w2, fmaf(x3.w, w3, a3))));
    }
    float acc4[4] = {a0, a1, a2, a3};
#pragma unroll
    for (int r = 0; r < 4; r++)
        g_bcp[((size_t)ks * ML + (row + r)) * 32 + c] = acc4[r];
}

// reduce partials -> g_BC2[t][j] = {B_j, C_j, B_{j+8}, C_{j+8}}
__global__ void __launch_bounds__(256)
bc_pack()
{
    const int t = blockIdx.x * 256 + threadIdx.x;   // over ML*8
    if (t >= ML * 8) return;
    const int row = t >> 3;
    const int j   = t & 7;
    float b0 = 0.f, c0 = 0.f, b8 = 0.f, c8 = 0.f;
#pragma unroll
    for (int ks = 0; ks < KSPL; ks++) {
        const float* p = &g_bcp[((size_t)ks * ML + row) * 32];
        b0 += p[j];      c0 += p[16 + j];
        b8 += p[8 + j];  c8 += p[24 + j];
    }
    g_BC2[(size_t)row * 8 + j] = make_float4(b0, c0, b8, c8);
}

// ---------------- chunked selective scan --------------------------------------
// 8 lanes per channel; lane n handles states n and n+8.
__global__ void __launch_bounds__(128)
scanA_kernel(const float* __restrict__ A_log)
{
    const int grp = threadIdx.x >> 3;        // 0..15 within block
    const int n   = threadIdx.x & 7;
    const int idx = blockIdx.x * 16 + grp;   // (g*BB+b)*DI + d
    const int d   = idx % DI;
    const int t   = idx / DI;
    const int b   = t % BB;
    const int g   = t / BB;

    const float a0 = -__expf(A_log[d * DS + n]);
    const float a1 = -__expf(A_log[d * DS + n + 8]);
    float h0 = 0.f, h1 = 0.f, sdt = 0.f;
    const int base = b * LL + g * LC;

    float4 dx = g_dx [(size_t)base * DI + d];
    float4 bc = g_BC2[(size_t)base * 8 + n];

    for (int i = 0; i < LC; i++) {
        const float4 dxc = dx;
        const float4 bcc = bc;
        if (i + 1 < LC) {
            const int rb = base + i + 1;
            dx = g_dx [(size_t)rb * DI + d];
            bc = g_BC2[(size_t)rb * 8 + n];
        }
        const float dtxc = dxc.x * dxc.y;
        h0 = fmaf(__expf(dxc.x * a0), h0, dtxc * bcc.x);
        h1 = fmaf(__expf(dxc.x * a1), h1, dtxc * bcc.z);
        sdt += dxc.x;
    }
    g_h0[(size_t)idx * DS + n]     = h0;
    g_h0[(size_t)idx * DS + n + 8] = h1;
    g_P [(size_t)idx * DS + n]     = __expf(a0 * sdt);
    g_P [(size_t)idx * DS + n + 8] = __expf(a1 * sdt);
}

__global__ void __launch_bounds__(256)
scanB_kernel()
{
    const int i = blockIdx.x * 256 + threadIdx.x;   // over BB*DI*DS
    const int n = i & 15;
    const int r = i >> 4;
    const int d = r % DI;
    const int b = r / DI;

    float h = 0.f;
#pragma unroll
    for (int g = 0; g < GSEG; g++) {
        const size_t j = (size_t)(((g * BB + b) * DI) + d) * DS + n;
        g_hin[j] = h;
        h = fmaf(g_P[j], h, g_h0[j]);
    }
}

__global__ void __launch_bounds__(128)
scanC_kernel(const float* __restrict__ A_log, const float* __restrict__ Dp)
{
    const int grp = threadIdx.x >> 3;
    const int n   = threadIdx.x & 7;
    const int idx = blockIdx.x * 16 + grp;
    const int d   = idx % DI;
    const int t   = idx / DI;
    const int b   = t % BB;
    const int g   = t / BB;

    const float a0 = -__expf(A_log[d * DS + n]);
    const float a1 = -__expf(A_log[d * DS + n + 8]);
    const float Dv = Dp[d];
    float h0 = g_hin[(size_t)idx * DS + n];
    float h1 = g_hin[(size_t)idx * DS + n + 8];
    const int base = b * LL + g * LC;

    float4 dx = g_dx [(size_t)base * DI + d];
    float4 bc = g_BC2[(size_t)base * 8 + n];

    for (int i = 0; i < LC; i++) {
        const float4 dxc = dx;
        const float4 bcc = bc;
        if (i + 1 < LC) {
            const int rb = base + i + 1;
            dx = g_dx [(size_t)rb * DI + d];
            bc = g_BC2[(size_t)rb * 8 + n];
        }

        const float dtxc = dxc.x * dxc.y;
        h0 = fmaf(__expf(dxc.x * a0), h0, dtxc * bcc.x);
        h1 = fmaf(__expf(dxc.x * a1), h1, dtxc * bcc.z);

        float p = h0 * bcc.y + h1 * bcc.w;
        p += __shfl_xor_sync(0xffffffffu, p, 4);
        p += __shfl_xor_sync(0xffffffffu, p, 2);
        p += __shfl_xor_sync(0xffffffffu, p, 1);

        if (n == 0) {
            const float z_c = dxc.z;
            const float sig = 1.f / (1.f + __expf(-z_c));
            const float y = (p + dxc.y * Dv) * (z_c * sig);
            g_y16[(size_t)(base + i) * DI + d] = __float2half(y);
        }
    }
}

// ---------------- launch ------------------------------------------------------
extern "C" void kernel_launch(void* const* d_in, const int* in_sizes, int n_in,
                              void* d_out, int out_size)
{
    const float* x      = (const float*)d_in[0];
    const float* W_in   = (const float*)d_in[1];
    const float* W_conv = (const float*)d_in[2];
    const float* b_conv = (const float*)d_in[3];
    const float* W_x    = (const float*)d_in[4];
    const float* W_dt   = (const float*)d_in[5];
    const float* b_dt   = (const float*)d_in[6];
    const float* A_log  = (const float*)d_in[7];
    const float* Dp     = (const float*)d_in[8];
    const float* W_out  = (const float*)d_in[9];
    float* out = (float*)d_out;

    const int smem_bytes = STAGES * (ATB + BTB);   // 98304
    cudaFuncSetAttribute(gemm_f16<1>, cudaFuncAttributeMaxDynamicSharedMemorySize, smem_bytes);
    cudaFuncSetAttribute(gemm_f16<2>, cudaFuncAttributeMaxDynamicSharedMemorySize, smem_bytes);
    cudaFuncSetAttribute(gemm_f16<3>, cudaFuncAttributeMaxDynamicSharedMemorySize, smem_bytes);

    // 0) fused fp32 -> fp16 casts
    const int ctot = N0 + N1 + N2 + N3;
    cvt_all<<<(ctot + 255) / 256, 256>>>(x, W_in, W_dt, W_out);

    // 1) xz = x @ W_in -> split g_xin / g_z
    gemm_f16<1><<<dim3(2 * DI / 128, ML / 128), 256, smem_bytes>>>(nullptr, nullptr,
                                                                   2 * DI, DM);
    // 2) depthwise causal conv + SiLU
    conv_kernel<<<(ML * DI) / 256, 256>>>(W_conv, b_conv);
    // 3) BC = xc @ W_x -> split-K partials + pack (reordered for 8-lane scan)
    bc_partial<<<(ML / 4) * KSPL / 8, 256>>>(W_x);
    bc_pack<<<(ML * 8 + 255) / 256, 256>>>();
    // 4) dt = softplus(xc @ W_dt + b_dt) -> packed {dt, xc, z}
    gemm_f16<2><<<dim3(DI / 128, ML / 128), 256, smem_bytes>>>(nullptr, b_dt,
                                                               DI, DI);
    // 5) chunked selective scan (8 lanes/channel, 2 states/lane)
    scanA_kernel<<<(GSEG * BB * DI) / 16, 128>>>(A_log);
    scanB_kernel<<<(BB * DI * DS) / 256, 256>>>();
    scanC_kernel<<<(GSEG * BB * DI) / 16, 128>>>(A_log, Dp);
    // 6) out = y @ W_out
    gemm_f16<3><<<dim3(DM / 128, ML / 128), 256, smem_bytes>>>(out, nullptr,
                                                               DM, DI);
}

// round 13
// speedup vs baseline: 7.8174x; 1.0937x over previous
#include <cuda_runtime.h>
#include <cuda_fp16.h>

// Problem constants (fixed by the reference)
#define BB 2
#define LL 2048
#define DM 768
#define DI 1536
#define DS 16
#define DC 4
#define ML (BB*LL)          // 4096 rows
#define GSEG 32             // scan segments
#define LC (LL/GSEG)        // 64 steps per segment
#define NDX 1664            // gemm2 padded N: 1536 (W_dt) + 32 (W_x) + 96 pad

// ---------------- scratch (device globals; no allocs allowed) ----------------
__device__ float  g_xin[ML*DI];
__device__ float  g_z  [ML*DI];
__device__ float  g_xc [ML*DI];
__device__ float4 g_BC2[ML*8];     // [t][j]: {B_j, C_j, B_{j+8}, C_{j+8}}
__device__ float4 g_dx [ML*DI];    // {dt, xc, z, 0} packed
__device__ float  g_bcp[ML*32];    // raw BC from gemm2 epilogue
__device__ float  g_h0 [GSEG*BB*DI*DS];
__device__ float  g_P  [GSEG*BB*DI*DS];
__device__ float  g_hin[GSEG*BB*DI*DS];
// fp16 operands
__device__ __align__(16) __half g_x16  [ML*DM];
__device__ __align__(16) __half g_xc16 [ML*DI];
__device__ __align__(16) __half g_y16  [ML*DI];
__device__ __align__(16) __half g_win16[DM*2*DI];
__device__ __align__(16) __half g_wdtx16[DI*NDX];   // [W_dt | W_x | 0-pad]
__device__ __align__(16) __half g_wout16[DI*DM];

// ---------------- helpers -----------------------------------------------------
__device__ __forceinline__ unsigned s2u(const void* p) {
    return (unsigned)__cvta_generic_to_shared(p);
}
__device__ __forceinline__ void cp16(unsigned sdst, const void* src) {
    asm volatile("cp.async.cg.shared.global [%0], [%1], 16;" :: "r"(sdst), "l"(src));
}

#define LDSM_X4(r0,r1,r2,r3,addr) \
    asm volatile("ldmatrix.sync.aligned.m8n8.x4.shared.b16 {%0,%1,%2,%3}, [%4];" \
        : "=r"(r0), "=r"(r1), "=r"(r2), "=r"(r3) : "r"(addr))
#define LDSM_X4T(r0,r1,r2,r3,addr) \
    asm volatile("ldmatrix.sync.aligned.m8n8.x4.trans.shared.b16 {%0,%1,%2,%3}, [%4];" \
        : "=r"(r0), "=r"(r1), "=r"(r2), "=r"(r3) : "r"(addr))

__device__ __forceinline__ void mma16816(float* c, const unsigned* a, const unsigned* b)
{
    asm volatile(
        "mma.sync.aligned.m16n8k16.row.col.f32.f16.f16.f32 "
        "{%0,%1,%2,%3}, {%4,%5,%6,%7}, {%8,%9}, {%0,%1,%2,%3};"
        : "+f"(c[0]), "+f"(c[1]), "+f"(c[2]), "+f"(c[3])
        : "r"(a[0]), "r"(a[1]), "r"(a[2]), "r"(a[3]), "r"(b[0]), "r"(b[1]));
}

__device__ __forceinline__ float softplusf(float v) {
    return fmaxf(v, 0.f) + log1pf(__expf(-fabsf(v)));
}

// ---------------- fused fp32 -> fp16 casts ------------------------------------
#define N0 (ML*DM/4)
#define N1 (DM*2*DI/4)
#define N2 (DI*NDX/4)
#define N3 (DI*DM/4)
__global__ void __launch_bounds__(256)
cvt_all(const float* __restrict__ x, const float* __restrict__ win,
        const float* __restrict__ wdt, const float* __restrict__ wx,
        const float* __restrict__ wout)
{
    const int t = blockIdx.x * 256 + threadIdx.x;
    if (t < N0) {
        const int i = t * 4;
        float4 v = *(const float4*)&x[i];
        __half2* d2 = (__half2*)&g_x16[i];
        d2[0] = __floats2half2_rn(v.x, v.y);
        d2[1] = __floats2half2_rn(v.z, v.w);
    } else if (t < N0 + N1) {
        const int i = (t - N0) * 4;
        float4 v = *(const float4*)&win[i];
        __half2* d2 = (__half2*)&g_win16[i];
        d2[0] = __floats2half2_rn(v.x, v.y);
        d2[1] = __floats2half2_rn(v.z, v.w);
    } else if (t < N0 + N1 + N2) {
        const int i = (t - N0 - N1) * 4;    // index into [DI][NDX]
        const int k = i / NDX;
        const int n = i % NDX;              // 4-groups never straddle 1536/1568
        float4 v;
        if (n < DI)            v = *(const float4*)&wdt[k * DI + n];
        else if (n < DI + 32)  v = *(const float4*)&wx[k * 32 + (n - DI)];
        else                   v = make_float4(0.f, 0.f, 0.f, 0.f);
        __half2* d2 = (__half2*)&g_wdtx16[i];
        d2[0] = __floats2half2_rn(v.x, v.y);
        d2[1] = __floats2half2_rn(v.z, v.w);
    } else if (t < N0 + N1 + N2 + N3) {
        const int i = (t - N0 - N1 - N2) * 4;
        float4 v = *(const float4*)&wout[i];
        __half2* d2 = (__half2*)&g_wout16[i];
        d2[0] = __floats2half2_rn(v.x, v.y);
        d2[1] = __floats2half2_rn(v.z, v.w);
    }
}

// ---------------- fp16 tensor GEMM: 128x128 tile, BK=64, 3-stage cp.async -----
// MODE 1: A=g_x16,  B=g_win16,   out -> split g_xin / g_z        (N=3072, K=768)
// MODE 2: A=g_xc16, B=g_wdtx16,  out -> g_dx pack / raw BC       (N=1664, K=1536)
// MODE 3: A=g_y16,  B=g_wout16,  out -> d_out                    (N=768,  K=1536)
#define STAGES 3
#define ATB 16384
#define BTB 16384

template <int MODE>
__global__ void __launch_bounds__(256, 2)
gemm_f16(float* __restrict__ C0, const float* __restrict__ bias, int N, int K)
{
    const __half* __restrict__ A =
        (MODE == 1) ? g_x16 : (MODE == 2) ? g_xc16 : g_y16;
    const __half* __restrict__ B =
        (MODE == 1) ? g_win16 : (MODE == 2) ? g_wdtx16 : g_wout16;

    extern __shared__ char sm[];
    char* Asm = sm;
    char* Bsm = sm + STAGES * ATB;

    const int tid  = threadIdx.x;
    const int lane = tid & 31;
    const int warp = tid >> 5;
    const int gid  = lane >> 2;
    const int tig  = lane & 3;
    const int wm   = (warp >> 2) * 64;
    const int wn   = (warp & 3) * 32;

    const int bm = blockIdx.y * 128;
    const int bn = blockIdx.x * 128;
    const int nt = K / 64;

    auto load_tile = [&](int kt, int s) {
        char* as = Asm + s * ATB;
        char* bs = Bsm + s * BTB;
#pragma unroll
        for (int it = 0; it < 4; it++) {
            const int q = tid + it * 256;
            const int r = q >> 3, c = q & 7;
            cp16(s2u(as) + r * 128 + ((c ^ (r & 7)) << 4),
                 A + (size_t)(bm + r) * K + kt + c * 8);
        }
#pragma unroll
        for (int it = 0; it < 4; it++) {
            const int q = tid + it * 256;
            const int r = q >> 4, c = q & 15;
            cp16(s2u(bs) + r * 256 + ((c ^ (r & 7)) << 4),
                 B + (size_t)(kt + r) * N + bn + c * 8);
        }
    };

    load_tile(0, 0);
    asm volatile("cp.async.commit_group;");
    load_tile(64, 1);
    asm volatile("cp.async.commit_group;");

    float acc[4][4][4];
#pragma unroll
    for (int i = 0; i < 4; i++)
#pragma unroll
        for (int j = 0; j < 4; j++)
#pragma unroll
            for (int q = 0; q < 4; q++) acc[i][j][q] = 0.f;

    for (int i = 0; i < nt; i++) {
        asm volatile("cp.async.wait_group 1;");
        __syncthreads();

        if (i + 2 < nt) load_tile((i + 2) * 64, (i + 2) % STAGES);
        asm volatile("cp.async.commit_group;");

        const unsigned asb = s2u(Asm + (i % STAGES) * ATB);
        const unsigned bsb = s2u(Bsm + (i % STAGES) * BTB);

#pragma unroll
        for (int ks = 0; ks < 4; ks++) {
            unsigned af[4][4];
#pragma unroll
            for (int mt = 0; mt < 4; mt++) {
                const int row = wm + mt * 16 + (lane & 15);
                const unsigned ad = asb + row * 128
                                  + (((2 * ks + (lane >> 4)) ^ (row & 7)) << 4);
                LDSM_X4(af[mt][0], af[mt][1], af[mt][2], af[mt][3], ad);
            }
            unsigned bf[4][2];
#pragma unroll
            for (int p = 0; p < 2; p++) {
                const int krow = ks * 16 + (lane & 15);
                const int nch = (wn >> 3) + p * 2 + (lane >> 4);
                const unsigned bd = bsb + krow * 256 + ((nch ^ (krow & 7)) << 4);
                LDSM_X4T(bf[2 * p][0], bf[2 * p][1], bf[2 * p + 1][0], bf[2 * p + 1][1], bd);
            }
#pragma unroll
            for (int mt = 0; mt < 4; mt++)
#pragma unroll
                for (int nn = 0; nn < 4; nn++)
                    mma16816(acc[mt][nn], af[mt], bf[nn]);
        }
    }

    // ---- vectorized epilogue ----
#pragma unroll
    for (int mt = 0; mt < 4; mt++) {
#pragma unroll
        for (int nn = 0; nn < 4; nn++) {
            const int c0 = bn + wn + nn * 8 + 2 * tig;
#pragma unroll
            for (int rh = 0; rh < 2; rh++) {
                const int r = bm + wm + mt * 16 + gid + rh * 8;
                const float v0 = acc[mt][nn][rh * 2 + 0];
                const float v1 = acc[mt][nn][rh * 2 + 1];
                if (MODE == 1) {
                    if (c0 < DI)
                        *(float2*)&g_xin[(size_t)r * DI + c0] = make_float2(v0, v1);
                    else
                        *(float2*)&g_z[(size_t)r * DI + (c0 - DI)] = make_float2(v0, v1);
                } else if (MODE == 2) {
                    if (c0 < DI) {
                        const float2 bz  = *(const float2*)&bias[c0];
                        const float2 xcv = *(const float2*)&g_xc[(size_t)r * DI + c0];
                        const float2 zv  = *(const float2*)&g_z [(size_t)r * DI + c0];
                        g_dx[(size_t)r * DI + c0]     = make_float4(softplusf(v0 + bz.x), xcv.x, zv.x, 0.f);
                        g_dx[(size_t)r * DI + c0 + 1] = make_float4(softplusf(v1 + bz.y), xcv.y, zv.y, 0.f);
                    } else if (c0 < DI + 32) {
                        *(float2*)&g_bcp[(size_t)r * 32 + (c0 - DI)] = make_float2(v0, v1);
                    }
                } else {
                    *(float2*)&C0[(size_t)r * DM + c0] = make_float2(v0, v1);
                }
            }
        }
    }
}

// ---------------- depthwise causal conv: 4 timesteps per thread ----------------
__global__ void __launch_bounds__(256)
conv_kernel(const float* __restrict__ W_conv, const float* __restrict__ b_conv)
{
    const int idx = blockIdx.x * 256 + threadIdx.x;   // over (ML/4)*DI
    const int d  = idx % DI;
    const int tq = idx / DI;
    const int t0 = tq * 4;
    const int l0 = t0 % LL;

    const float w0 = W_conv[d * DC + 0];
    const float w1 = W_conv[d * DC + 1];
    const float w2 = W_conv[d * DC + 2];
    const float w3 = W_conv[d * DC + 3];
    const float bb = b_conv[d];

    float xv[7];
#pragma unroll
    for (int j = 0; j < 7; j++) {
        const int l = l0 + j - 3;
        xv[j] = (l >= 0) ? g_xin[(size_t)(t0 + j - 3) * DI + d] : 0.f;
    }
#pragma unroll
    for (int i = 0; i < 4; i++) {
        float acc = bb;
        acc = fmaf(xv[i],     w0, acc);
        acc = fmaf(xv[i + 1], w1, acc);
        acc = fmaf(xv[i + 2], w2, acc);
        acc = fmaf(xv[i + 3], w3, acc);
        const float sig = 1.f / (1.f + __expf(-acc));
        const float v = acc * sig;
        g_xc  [(size_t)(t0 + i) * DI + d] = v;
        g_xc16[(size_t)(t0 + i) * DI + d] = __float2half(v);
    }
}

// reorder raw BC -> g_BC2[t][j] = {B_j, C_j, B_{j+8}, C_{j+8}}
__global__ void __launch_bounds__(256)
bc_pack()
{
    const int t = blockIdx.x * 256 + threadIdx.x;   // over ML*8
    if (t >= ML * 8) return;
    const int row = t >> 3;
    const int j   = t & 7;
    const float* p = &g_bcp[(size_t)row * 32];
    g_BC2[(size_t)row * 8 + j] = make_float4(p[j], p[16 + j], p[8 + j], p[24 + j]);
}

// ---------------- chunked selective scan --------------------------------------
// 8 lanes per channel; lane n handles states n and n+8.
__global__ void __launch_bounds__(128)
scanA_kernel(const float* __restrict__ A_log)
{
    const int grp = threadIdx.x >> 3;        // 0..15 within block
    const int n   = threadIdx.x & 7;
    const int idx = blockIdx.x * 16 + grp;   // (g*BB+b)*DI + d
    const int d   = idx % DI;
    const int t   = idx / DI;
    const int b   = t % BB;
    const int g   = t / BB;

    const float a0 = -__expf(A_log[d * DS + n]);
    const float a1 = -__expf(A_log[d * DS + n + 8]);
    float h0 = 0.f, h1 = 0.f, sdt = 0.f;
    const int base = b * LL + g * LC;

    float4 dx = g_dx [(size_t)base * DI + d];
    float4 bc = g_BC2[(size_t)base * 8 + n];

    for (int i = 0; i < LC; i++) {
        const float4 dxc = dx;
        const float4 bcc = bc;
        if (i + 1 < LC) {
            const int rb = base + i + 1;
            dx = g_dx [(size_t)rb * DI + d];
            bc = g_BC2[(size_t)rb * 8 + n];
        }
        const float dtxc = dxc.x * dxc.y;
        h0 = fmaf(__expf(dxc.x * a0), h0, dtxc * bcc.x);
        h1 = fmaf(__expf(dxc.x * a1), h1, dtxc * bcc.z);
        sdt += dxc.x;
    }
    g_h0[(size_t)idx * DS + n]     = h0;
    g_h0[(size_t)idx * DS + n + 8] = h1;
    g_P [(size_t)idx * DS + n]     = __expf(a0 * sdt);
    g_P [(size_t)idx * DS + n + 8] = __expf(a1 * sdt);
}

__global__ void __launch_bounds__(256)
scanB_kernel()
{
    const int i = blockIdx.x * 256 + threadIdx.x;   // over BB*DI*DS
    const int n = i & 15;
    const int r = i >> 4;
    const int d = r % DI;
    const int b = r / DI;

    float h = 0.f;
#pragma unroll
    for (int g = 0; g < GSEG; g++) {
        const size_t j = (size_t)(((g * BB + b) * DI) + d) * DS + n;
        g_hin[j] = h;
        h = fmaf(g_P[j], h, g_h0[j]);
    }
}

__global__ void __launch_bounds__(128)
scanC_kernel(const float* __restrict__ A_log, const float* __restrict__ Dp)
{
    const int grp = threadIdx.x >> 3;
    const int n   = threadIdx.x & 7;
    const int idx = blockIdx.x * 16 + grp;
    const int d   = idx % DI;
    const int t   = idx / DI;
    const int b   = t % BB;
    const int g   = t / BB;

    const float a0 = -__expf(A_log[d * DS + n]);
    const float a1 = -__expf(A_log[d * DS + n + 8]);
    const float Dv = Dp[d];
    float h0 = g_hin[(size_t)idx * DS + n];
    float h1 = g_hin[(size_t)idx * DS + n + 8];
    const int base = b * LL + g * LC;

    float4 dx = g_dx [(size_t)base * DI + d];
    float4 bc = g_BC2[(size_t)base * 8 + n];

    for (int i = 0; i < LC; i++) {
        const float4 dxc = dx;
        const float4 bcc = bc;
        if (i + 1 < LC) {
            const int rb = base + i + 1;
            dx = g_dx [(size_t)rb * DI + d];
            bc = g_BC2[(size_t)rb * 8 + n];
        }

        const float dtxc = dxc.x * dxc.y;
        h0 = fmaf(__expf(dxc.x * a0), h0, dtxc * bcc.x);
        h1 = fmaf(__expf(dxc.x * a1), h1, dtxc * bcc.z);

        float p = h0 * bcc.y + h1 * bcc.w;
        p += __shfl_xor_sync(0xffffffffu, p, 4);
        p += __shfl_xor_sync(0xffffffffu, p, 2);
        p += __shfl_xor_sync(0xffffffffu, p, 1);

        if (n == 0) {
            const float z_c = dxc.z;
            const float sig = 1.f / (1.f + __expf(-z_c));
            const float y = (p + dxc.y * Dv) * (z_c * sig);
            g_y16[(size_t)(base + i) * DI + d] = __float2half(y);
        }
    }
}

// ---------------- launch ------------------------------------------------------
extern "C" void kernel_launch(void* const* d_in, const int* in_sizes, int n_in,
                              void* d_out, int out_size)
{
    const float* x      = (const float*)d_in[0];
    const float* W_in   = (const float*)d_in[1];
    const float* W_conv = (const float*)d_in[2];
    const float* b_conv = (const float*)d_in[3];
    const float* W_x    = (const float*)d_in[4];
    const float* W_dt   = (const float*)d_in[5];
    const float* b_dt   = (const float*)d_in[6];
    const float* A_log  = (const float*)d_in[7];
    const float* Dp     = (const float*)d_in[8];
    const float* W_out  = (const float*)d_in[9];
    float* out = (float*)d_out;

    const int smem_bytes = STAGES * (ATB + BTB);   // 98304
    cudaFuncSetAttribute(gemm_f16<1>, cudaFuncAttributeMaxDynamicSharedMemorySize, smem_bytes);
    cudaFuncSetAttribute(gemm_f16<2>, cudaFuncAttributeMaxDynamicSharedMemorySize, smem_bytes);
    cudaFuncSetAttribute(gemm_f16<3>, cudaFuncAttributeMaxDynamicSharedMemorySize, smem_bytes);

    // 0) fused fp32 -> fp16 casts (builds padded [W_dt | W_x] weights)
    const int ctot = N0 + N1 + N2 + N3;
    cvt_all<<<(ctot + 255) / 256, 256>>>(x, W_in, W_dt, W_x, W_out);

    // 1) xz = x @ W_in -> split g_xin / g_z
    gemm_f16<1><<<dim3(2 * DI / 128, ML / 128), 256, smem_bytes>>>(nullptr, nullptr,
                                                                   2 * DI, DM);
    // 2) depthwise causal conv + SiLU (4 timesteps/thread)
    conv_kernel<<<(ML / 4) * DI / 256, 256>>>(W_conv, b_conv);
    // 3+4) fused: [dt | BC] = xc @ [W_dt | W_x]; dt -> softplus -> g_dx, BC raw
    gemm_f16<2><<<dim3(NDX / 128, ML / 128), 256, smem_bytes>>>(nullptr, b_dt,
                                                                NDX, DI);
    bc_pack<<<(ML * 8 + 255) / 256, 256>>>();
    // 5) chunked selective scan (8 lanes/channel, 2 states/lane)
    scanA_kernel<<<(GSEG * BB * DI) / 16, 128>>>(A_log);
    scanB_kernel<<<(BB * DI * DS) / 256, 256>>>();
    scanC_kernel<<<(GSEG * BB * DI) / 16, 128>>>(A_log, Dp);
    // 6) out = y @ W_out
    gemm_f16<3><<<dim3(DM / 128, ML / 128), 256, smem_bytes>>>(out, nullptr,
                                                               DM, DI);
}